// round 2
// baseline (speedup 1.0000x reference)
#include <cuda_runtime.h>
#include <math.h>

#define BATCH   1024
#define NSEQ    50
#define RCNT    1000
#define NPOIS   50000
#define DD      128
#define XST     132   // x_s row stride (floats), float4-friendly
#define QST     133   // Q/K/V row stride, conflict-free scalar access
#define AST     52    // attn row stride
#define DEG2RAD 0.017453292519943295f
#define SCALE   0.08838834764831845f  // 1/sqrt(128)

// scratch: S = attn @ V, (B, N, D) fp32
__device__ float g_S[BATCH * NSEQ * DD];

__device__ __forceinline__ float interp64(const float* t, float x) {
    x = fminf(fmaxf(x, 0.f), 62.999996f);
    int k = (int)x;
    float f = x - (float)k;
    return t[k] + f * (t[k + 1] - t[k]);
}

// haversine distance (km) with small-angle polynomials (exact to fp32 for
// lat/lon in [0,1] deg): sin(x)~x(1-x^2/6), asin(s)~s(1+a/6), cos precomputed.
__device__ __forceinline__ float hav_dist(float lat1, float lon1, float c1,
                                          float lat2, float lon2, float c2) {
    float hl = (lat2 - lat1) * (0.5f * DEG2RAD);
    float sl = hl * (1.f - hl * hl * (1.f / 6.f));
    float ho = (lon2 - lon1) * (0.5f * DEG2RAD);
    float so = ho * (1.f - ho * ho * (1.f / 6.f));
    float a = sl * sl + c1 * c2 * so * so;
    a = fminf(fmaxf(a, 0.f), 1.f);
    float s = sqrtf(a);
    return 12742.f * s * (1.f + a * (1.f / 6.f));
}

__device__ __forceinline__ float coslat(float latdeg) {
    float r = latdeg * DEG2RAD;
    float r2 = r * r;
    return 1.f - 0.5f * r2 + r2 * r2 * (1.f / 24.f);
}

// one 50x128 @ 128x128^T projection: out[n][d] = sum_k x[n][k] * W[d][k]
__device__ __forceinline__ void proj_one(const float* __restrict__ W,
                                         float* __restrict__ O,
                                         const float* __restrict__ x_s,
                                         int d, int nh) {
    const float4* wrow = (const float4*)(W + d * DD);
    float acc[25];
#pragma unroll
    for (int i = 0; i < 25; i++) acc[i] = 0.f;
#pragma unroll 2
    for (int k4 = 0; k4 < 32; k4++) {
        float4 wv = wrow[k4];
#pragma unroll
        for (int i = 0; i < 25; i++) {
            int n = nh + 2 * i;
            float4 xv = *(const float4*)&x_s[n * XST + k4 * 4];
            acc[i] = fmaf(xv.x, wv.x, acc[i]);
            acc[i] = fmaf(xv.y, wv.y, acc[i]);
            acc[i] = fmaf(xv.z, wv.z, acc[i]);
            acc[i] = fmaf(xv.w, wv.w, acc[i]);
        }
    }
#pragma unroll
    for (int i = 0; i < 25; i++) O[(nh + 2 * i) * QST + d] = acc[i];
}

// ---------------- Kernel 1: gather + QKV + biased attention -> S ----------------
// grid = B, block = 256, dyn smem = 107712 B
__global__ __launch_bounds__(256, 2)
void attn_kernel(const int* __restrict__ poi_idx, const int* __restrict__ hour,
                 const float* __restrict__ lat, const float* __restrict__ lon,
                 const float* __restrict__ t_min,
                 const float* __restrict__ poi_emb, const float* __restrict__ time_emb,
                 const float* __restrict__ E_t, const float* __restrict__ E_d,
                 const float* __restrict__ Wq, const float* __restrict__ Wk,
                 const float* __restrict__ Wv) {
    extern __shared__ float sm[];
    float* x_s  = sm;                 // 50*132 = 6600 (aliased as attn later)
    float* Q_s  = sm + 6600;          // 50*133 = 6650
    float* K_s  = Q_s + 6650;
    float* V_s  = K_s + 6650;
    float* tv   = V_s + 6650;         // 50
    float* la   = tv + 50;
    float* lo   = la + 50;
    float* cl   = lo + 50;
    float* padf = cl + 50;
    float* Et_s = padf + 50;          // 64
    float* Ed_s = Et_s + 64;          // 64
    float* attn_s = x_s;              // 50*52 alias

    int b = blockIdx.x;
    int tid = threadIdx.x;

    if (tid < 64) { Et_s[tid] = E_t[tid]; Ed_s[tid] = E_d[tid]; }
    if (tid < NSEQ) {
        int pi = poi_idx[b * NSEQ + tid];
        padf[tid] = (pi < 0) ? 1.f : 0.f;
        tv[tid] = t_min[b * NSEQ + tid];
        float lt = lat[b * NSEQ + tid];
        la[tid] = lt;
        lo[tid] = lon[b * NSEQ + tid];
        cl[tid] = coslat(lt);
    }
    for (int idx = tid; idx < NSEQ * DD; idx += 256) {
        int n = idx >> 7, d = idx & 127;
        int pi = poi_idx[b * NSEQ + n];
        int ps, hs;
        if (pi < 0) { ps = NPOIS; hs = 0; }
        else        { ps = pi;    hs = hour[b * NSEQ + n]; }
        x_s[n * XST + d] = poi_emb[ps * DD + d] + time_emb[hs * DD + d];
    }
    __syncthreads();

    int d = tid & 127;
    int nh = tid >> 7;
    proj_one(Wq, Q_s, x_s, d, nh);
    proj_one(Wk, K_s, x_s, d, nh);
    proj_one(Wv, V_s, x_s, d, nh);
    __syncthreads();   // after this, x_s is dead -> reuse as attn_s

    // scores + bias + row softmax (warp per row; lane covers m and m+32)
    int warp = tid >> 5, lane = tid & 31;
    const float NEGINF = -__int_as_float(0x7f800000) * 0.f - 1e38f; // large neg
    for (int n = warp; n < NSEQ; n += 8) {
        int m1 = lane, m2 = lane + 32;
        bool v2 = (m2 < NSEQ);
        float a1 = 0.f, a2 = 0.f;
        const float* qrow = &Q_s[n * QST];
        const float* k1 = &K_s[m1 * QST];
        const float* k2 = &K_s[(v2 ? m2 : 0) * QST];
#pragma unroll 8
        for (int k = 0; k < DD; k++) {
            float q = qrow[k];
            a1 = fmaf(q, k1[k], a1);
            a2 = fmaf(q, k2[k], a2);
        }
        float vpn = 1.f - padf[n];
        // bias for m1
        float s1, s2;
        {
            float vp = vpn * (1.f - padf[m1]);
            float dt = fabsf(tv[n] - tv[m1]) * vp;
            float dd = hav_dist(la[n], lo[n], cl[n], la[m1], lo[m1], cl[m1]) * vp;
            float bias = interp64(Et_s, dt * (63.f / 10080.f)) +
                         interp64(Ed_s, dd * (63.f / 200.f));
            s1 = a1 * SCALE + bias;
            if (padf[m1] > 0.5f) s1 = NEGINF;
        }
        if (v2) {
            float vp = vpn * (1.f - padf[m2]);
            float dt = fabsf(tv[n] - tv[m2]) * vp;
            float dd = hav_dist(la[n], lo[n], cl[n], la[m2], lo[m2], cl[m2]) * vp;
            float bias = interp64(Et_s, dt * (63.f / 10080.f)) +
                         interp64(Ed_s, dd * (63.f / 200.f));
            s2 = a2 * SCALE + bias;
            if (padf[m2] > 0.5f) s2 = NEGINF;
        } else {
            s2 = NEGINF;
        }
        float mx = fmaxf(s1, s2);
#pragma unroll
        for (int off = 16; off; off >>= 1)
            mx = fmaxf(mx, __shfl_xor_sync(0xffffffff, mx, off));
        float e1 = (s1 > -1e37f) ? __expf(s1 - mx) : 0.f;
        float e2 = (s2 > -1e37f) ? __expf(s2 - mx) : 0.f;
        float sum = e1 + e2;
#pragma unroll
        for (int off = 16; off; off >>= 1)
            sum += __shfl_xor_sync(0xffffffff, sum, off);
        float inv = (sum > 0.f) ? 1.f / sum : 0.f;
        attn_s[n * AST + m1] = e1 * inv;
        if (m2 < AST) attn_s[n * AST + m2] = v2 ? e2 * inv : 0.f;
    }
    __syncthreads();

    // S = attn @ V  (thread owns column d, 25 rows)
    {
        float acc[25];
#pragma unroll
        for (int i = 0; i < 25; i++) acc[i] = 0.f;
#pragma unroll 2
        for (int m4 = 0; m4 < 12; m4++) {
            float v0 = V_s[(m4 * 4 + 0) * QST + d];
            float v1 = V_s[(m4 * 4 + 1) * QST + d];
            float v2v = V_s[(m4 * 4 + 2) * QST + d];
            float v3 = V_s[(m4 * 4 + 3) * QST + d];
#pragma unroll
            for (int i = 0; i < 25; i++) {
                int n = nh + 2 * i;
                float4 av = *(const float4*)&attn_s[n * AST + m4 * 4];
                acc[i] = fmaf(av.x, v0, acc[i]);
                acc[i] = fmaf(av.y, v1, acc[i]);
                acc[i] = fmaf(av.z, v2v, acc[i]);
                acc[i] = fmaf(av.w, v3, acc[i]);
            }
        }
        {
            float v0 = V_s[48 * QST + d];
            float v1 = V_s[49 * QST + d];
#pragma unroll
            for (int i = 0; i < 25; i++) {
                int n = nh + 2 * i;
                acc[i] = fmaf(attn_s[n * AST + 48], v0, acc[i]);
                acc[i] = fmaf(attn_s[n * AST + 49], v1, acc[i]);
            }
        }
#pragma unroll
        for (int i = 0; i < 25; i++) {
            int n = nh + 2 * i;
            g_S[(b * NSEQ + n) * DD + d] = acc[i];
        }
    }
}

// ---------------- Kernel 2: match GEMM + bias + softmax over n ----------------
// grid = (8, B), block = 320, dyn smem = 122176 B
__global__ __launch_bounds__(320, 1)
void match_kernel(const int* __restrict__ poi_idx,
                  const float* __restrict__ lat, const float* __restrict__ lon,
                  const float* __restrict__ centroids,
                  const float* __restrict__ E_dm,
                  const float* __restrict__ region_emb,
                  float* __restrict__ out) {
    extern __shared__ float sm[];
    float* S_s   = sm;                 // 50*128 = 6400
    float* E_s   = sm + 6400;          // 128*132 = 16896 (transposed [k][j])
    float* ms_s  = E_s + 16896;        // 50*132 = 6600
    float* lan   = ms_s + 6600;        // 50
    float* lonn  = lan + 50;
    float* cn    = lonn + 50;
    float* pn    = cn + 50;
    float* lar   = pn + 50;            // 128
    float* lor   = lar + 128;
    float* cr    = lor + 128;
    float* Edm_s = cr + 128;           // 64

    int b = blockIdx.y;
    int r0 = blockIdx.x * 128;
    int tid = threadIdx.x;

    if (tid < 64) Edm_s[tid] = E_dm[tid];
    if (tid < NSEQ) {
        pn[tid] = (poi_idx[b * NSEQ + tid] < 0) ? 1.f : 0.f;
        float lt = lat[b * NSEQ + tid];
        lan[tid] = lt;
        lonn[tid] = lon[b * NSEQ + tid];
        cn[tid] = coslat(lt);
    }
    if (tid < 128) {
        int r = r0 + tid;
        float lt = 0.f, ln = 0.f;
        if (r < RCNT) { lt = centroids[2 * r]; ln = centroids[2 * r + 1]; }
        lar[tid] = lt; lor[tid] = ln; cr[tid] = coslat(lt);
    }
    for (int idx = tid; idx < NSEQ * DD; idx += 320)
        S_s[idx] = g_S[b * NSEQ * DD + idx];
    for (int idx = tid; idx < DD * DD; idx += 320) {
        int j = idx >> 7, k = idx & 127;
        int r = r0 + j;
        E_s[k * 132 + j] = (r < RCNT) ? region_emb[r * DD + k] : 0.f;
    }
    __syncthreads();

    // GEMM: C[n][j] = sum_k S[n][k] * E[j][k], 5n x 4j micro-tile per thread
    int jg = tid & 31, ng = tid >> 5;
    int j0 = jg * 4, n0 = ng * 5;
    float4 acc[5];
#pragma unroll
    for (int i = 0; i < 5; i++) acc[i] = make_float4(0.f, 0.f, 0.f, 0.f);
#pragma unroll 4
    for (int k = 0; k < DD; k++) {
        float4 e = *(const float4*)&E_s[k * 132 + j0];
#pragma unroll
        for (int i = 0; i < 5; i++) {
            float s = S_s[(n0 + i) * DD + k];
            acc[i].x = fmaf(s, e.x, acc[i].x);
            acc[i].y = fmaf(s, e.y, acc[i].y);
            acc[i].z = fmaf(s, e.z, acc[i].z);
            acc[i].w = fmaf(s, e.w, acc[i].w);
        }
    }
    // bias + store m_scores
#pragma unroll
    for (int i = 0; i < 5; i++) {
        int n = n0 + i;
        float vals[4] = {acc[i].x, acc[i].y, acc[i].z, acc[i].w};
#pragma unroll
        for (int jj = 0; jj < 4; jj++) {
            int j = j0 + jj;
            float dd = hav_dist(lan[n], lonn[n], cn[n], lar[j], lor[j], cr[j]);
            float bias = interp64(Edm_s, dd * (63.f / 200.f));
            ms_s[n * 132 + j] = vals[jj] * SCALE + bias;
        }
    }
    __syncthreads();

    // softmax over n per column + weighted score sum
    if (tid < 128 && r0 + tid < RCNT) {
        int j = tid;
        float mx = -1e38f;
        for (int n = 0; n < NSEQ; n++)
            if (pn[n] < 0.5f) mx = fmaxf(mx, ms_s[n * 132 + j]);
        float sum = 0.f, accv = 0.f;
        for (int n = 0; n < NSEQ; n++) {
            if (pn[n] < 0.5f) {
                float v = ms_s[n * 132 + j];
                float e = __expf(v - mx);
                sum += e;
                accv += e * v;
            }
        }
        out[b * RCNT + r0 + j] = (sum > 0.f) ? accv / sum : 0.f;
    }
}

extern "C" void kernel_launch(void* const* d_in, const int* in_sizes, int n_in,
                              void* d_out, int out_size) {
    const int*   poi_idx  = (const int*)d_in[0];
    const int*   hour     = (const int*)d_in[1];
    const float* lat      = (const float*)d_in[2];
    const float* lon      = (const float*)d_in[3];
    const float* t_min    = (const float*)d_in[4];
    const float* cent     = (const float*)d_in[5];
    const float* poi_emb  = (const float*)d_in[6];
    const float* time_emb = (const float*)d_in[7];
    const float* E_t      = (const float*)d_in[8];
    const float* E_d      = (const float*)d_in[9];
    const float* E_dm     = (const float*)d_in[10];
    const float* remb     = (const float*)d_in[11];
    const float* Wq       = (const float*)d_in[12];
    const float* Wk       = (const float*)d_in[13];
    const float* Wv       = (const float*)d_in[14];
    float* out = (float*)d_out;

    const int SMEM_A = 26928 * 4;   // 107712 B
    const int SMEM_B = 30544 * 4;   // 122176 B
    cudaFuncSetAttribute(attn_kernel,  cudaFuncAttributeMaxDynamicSharedMemorySize, SMEM_A);
    cudaFuncSetAttribute(match_kernel, cudaFuncAttributeMaxDynamicSharedMemorySize, SMEM_B);

    attn_kernel<<<BATCH, 256, SMEM_A>>>(poi_idx, hour, lat, lon, t_min,
                                        poi_emb, time_emb, E_t, E_d, Wq, Wk, Wv);
    match_kernel<<<dim3(8, BATCH), 320, SMEM_B>>>(poi_idx, lat, lon, cent,
                                                  E_dm, remb, out);
}

// round 6
// speedup vs baseline: 1.9921x; 1.9921x over previous
#include <cuda_runtime.h>
#include <cuda_bf16.h>
#include <cstdint>
#include <math.h>

#define BATCH   1024
#define NSEQ    50
#define RCNT    1000
#define NPOIS   50000
#define DD      128
#define XST     132   // x_s row stride (floats), float4-friendly
#define QST     133   // Q/K/V row stride, conflict-free scalar access
#define AST     52    // attn row stride
#define BST     136   // bf16 tile row stride (elements)
#define DEG2RAD 0.017453292519943295f
#define SCALE   0.08838834764831845f  // 1/sqrt(128)

// scratch: S = attn @ V, (B, N, D) fp32
__device__ __align__(16) float g_S[BATCH * NSEQ * DD];

__device__ __forceinline__ float interp64(const float* t, float x) {
    x = fminf(fmaxf(x, 0.f), 62.999996f);
    int k = (int)x;
    float f = x - (float)k;
    return t[k] + f * (t[k + 1] - t[k]);
}

// haversine distance (km) with small-angle polynomials (exact to fp32 for
// lat/lon in [0,1] deg)
__device__ __forceinline__ float hav_dist(float lat1, float lon1, float c1,
                                          float lat2, float lon2, float c2) {
    float hl = (lat2 - lat1) * (0.5f * DEG2RAD);
    float sl = hl * (1.f - hl * hl * (1.f / 6.f));
    float ho = (lon2 - lon1) * (0.5f * DEG2RAD);
    float so = ho * (1.f - ho * ho * (1.f / 6.f));
    float a = sl * sl + c1 * c2 * so * so;
    a = fminf(fmaxf(a, 0.f), 1.f);
    float s = sqrtf(a);
    return 12742.f * s * (1.f + a * (1.f / 6.f));
}

__device__ __forceinline__ float coslat(float latdeg) {
    float r = latdeg * DEG2RAD;
    float r2 = r * r;
    return 1.f - 0.5f * r2 + r2 * r2 * (1.f / 24.f);
}

__device__ __forceinline__ uint32_t smem_u32(const void* p) {
    return (uint32_t)__cvta_generic_to_shared(p);
}

#define LDMX4(R, addr)                                                        \
    asm volatile("ldmatrix.sync.aligned.m8n8.x4.shared.b16 {%0,%1,%2,%3}, [%4];" \
                 : "=r"((R)[0]), "=r"((R)[1]), "=r"((R)[2]), "=r"((R)[3])      \
                 : "r"(addr))

#define MMA16816(C, A, B0, B1)                                                \
    asm volatile("mma.sync.aligned.m16n8k16.row.col.f32.bf16.bf16.f32 "       \
                 "{%0,%1,%2,%3},{%4,%5,%6,%7},{%8,%9},{%0,%1,%2,%3};"         \
                 : "+f"((C)[0]), "+f"((C)[1]), "+f"((C)[2]), "+f"((C)[3])      \
                 : "r"((A)[0]), "r"((A)[1]), "r"((A)[2]), "r"((A)[3]),         \
                   "r"(B0), "r"(B1))

// one 50x128 @ 128x128^T projection: out[n][d] = sum_k x[n][k] * W[d][k]
__device__ __forceinline__ void proj_one(const float* __restrict__ W,
                                         float* __restrict__ O,
                                         const float* __restrict__ x_s,
                                         int d, int nh) {
    const float4* wrow = (const float4*)(W + d * DD);
    float acc[25];
#pragma unroll
    for (int i = 0; i < 25; i++) acc[i] = 0.f;
#pragma unroll 2
    for (int k4 = 0; k4 < 32; k4++) {
        float4 wv = wrow[k4];
#pragma unroll
        for (int i = 0; i < 25; i++) {
            int n = nh + 2 * i;
            float4 xv = *(const float4*)&x_s[n * XST + k4 * 4];
            acc[i] = fmaf(xv.x, wv.x, acc[i]);
            acc[i] = fmaf(xv.y, wv.y, acc[i]);
            acc[i] = fmaf(xv.z, wv.z, acc[i]);
            acc[i] = fmaf(xv.w, wv.w, acc[i]);
        }
    }
#pragma unroll
    for (int i = 0; i < 25; i++) O[(nh + 2 * i) * QST + d] = acc[i];
}

// ---------------- Kernel 1: gather + QKV + biased attention -> S ----------------
// grid = B, block = 256, dyn smem = 107712 B
__global__ __launch_bounds__(256, 2)
void attn_kernel(const int* __restrict__ poi_idx, const int* __restrict__ hour,
                 const float* __restrict__ lat, const float* __restrict__ lon,
                 const float* __restrict__ t_min,
                 const float* __restrict__ poi_emb, const float* __restrict__ time_emb,
                 const float* __restrict__ E_t, const float* __restrict__ E_d,
                 const float* __restrict__ Wq, const float* __restrict__ Wk,
                 const float* __restrict__ Wv) {
    extern __shared__ float sm[];
    float* x_s  = sm;                 // 50*132 = 6600 (aliased as attn later)
    float* Q_s  = sm + 6600;          // 50*133 = 6650
    float* K_s  = Q_s + 6650;
    float* V_s  = K_s + 6650;
    float* tv   = V_s + 6650;         // 50
    float* la   = tv + 50;
    float* lo   = la + 50;
    float* cl   = lo + 50;
    float* padf = cl + 50;
    float* Et_s = padf + 50;          // 64
    float* Ed_s = Et_s + 64;          // 64
    float* attn_s = x_s;              // 50*52 alias

    int b = blockIdx.x;
    int tid = threadIdx.x;

    if (tid < 64) { Et_s[tid] = E_t[tid]; Ed_s[tid] = E_d[tid]; }
    if (tid < NSEQ) {
        int pi = poi_idx[b * NSEQ + tid];
        padf[tid] = (pi < 0) ? 1.f : 0.f;
        tv[tid] = t_min[b * NSEQ + tid];
        float lt = lat[b * NSEQ + tid];
        la[tid] = lt;
        lo[tid] = lon[b * NSEQ + tid];
        cl[tid] = coslat(lt);
    }
    for (int idx = tid; idx < NSEQ * DD; idx += 256) {
        int n = idx >> 7, d = idx & 127;
        int pi = poi_idx[b * NSEQ + n];
        int ps, hs;
        if (pi < 0) { ps = NPOIS; hs = 0; }
        else        { ps = pi;    hs = hour[b * NSEQ + n]; }
        x_s[n * XST + d] = poi_emb[ps * DD + d] + time_emb[hs * DD + d];
    }
    __syncthreads();

    int d = tid & 127;
    int nh = tid >> 7;
    proj_one(Wq, Q_s, x_s, d, nh);
    proj_one(Wk, K_s, x_s, d, nh);
    proj_one(Wv, V_s, x_s, d, nh);
    __syncthreads();   // after this, x_s is dead -> reuse as attn_s

    // scores + bias + row softmax (warp per row; lane covers m and m+32)
    int warp = tid >> 5, lane = tid & 31;
    const float NEGINF = -1e38f;
    for (int n = warp; n < NSEQ; n += 8) {
        int m1 = lane, m2 = lane + 32;
        bool v2 = (m2 < NSEQ);
        float a1 = 0.f, a2 = 0.f;
        const float* qrow = &Q_s[n * QST];
        const float* k1 = &K_s[m1 * QST];
        const float* k2 = &K_s[(v2 ? m2 : 0) * QST];
#pragma unroll 8
        for (int k = 0; k < DD; k++) {
            float q = qrow[k];
            a1 = fmaf(q, k1[k], a1);
            a2 = fmaf(q, k2[k], a2);
        }
        float vpn = 1.f - padf[n];
        float s1, s2;
        {
            float vp = vpn * (1.f - padf[m1]);
            float dt = fabsf(tv[n] - tv[m1]) * vp;
            float dd = hav_dist(la[n], lo[n], cl[n], la[m1], lo[m1], cl[m1]) * vp;
            float bias = interp64(Et_s, dt * (63.f / 10080.f)) +
                         interp64(Ed_s, dd * (63.f / 200.f));
            s1 = a1 * SCALE + bias;
            if (padf[m1] > 0.5f) s1 = NEGINF;
        }
        if (v2) {
            float vp = vpn * (1.f - padf[m2]);
            float dt = fabsf(tv[n] - tv[m2]) * vp;
            float dd = hav_dist(la[n], lo[n], cl[n], la[m2], lo[m2], cl[m2]) * vp;
            float bias = interp64(Et_s, dt * (63.f / 10080.f)) +
                         interp64(Ed_s, dd * (63.f / 200.f));
            s2 = a2 * SCALE + bias;
            if (padf[m2] > 0.5f) s2 = NEGINF;
        } else {
            s2 = NEGINF;
        }
        float mx = fmaxf(s1, s2);
#pragma unroll
        for (int off = 16; off; off >>= 1)
            mx = fmaxf(mx, __shfl_xor_sync(0xffffffff, mx, off));
        float e1 = (s1 > -1e37f) ? __expf(s1 - mx) : 0.f;
        float e2 = (s2 > -1e37f) ? __expf(s2 - mx) : 0.f;
        float sum = e1 + e2;
#pragma unroll
        for (int off = 16; off; off >>= 1)
            sum += __shfl_xor_sync(0xffffffff, sum, off);
        float inv = (sum > 0.f) ? 1.f / sum : 0.f;
        attn_s[n * AST + m1] = e1 * inv;
        if (m2 < AST) attn_s[n * AST + m2] = v2 ? e2 * inv : 0.f;
    }
    __syncthreads();

    // S = attn @ V  (thread owns column d, 25 rows)
    {
        float acc[25];
#pragma unroll
        for (int i = 0; i < 25; i++) acc[i] = 0.f;
#pragma unroll 2
        for (int m4 = 0; m4 < 12; m4++) {
            float v0 = V_s[(m4 * 4 + 0) * QST + d];
            float v1 = V_s[(m4 * 4 + 1) * QST + d];
            float v2v = V_s[(m4 * 4 + 2) * QST + d];
            float v3 = V_s[(m4 * 4 + 3) * QST + d];
#pragma unroll
            for (int i = 0; i < 25; i++) {
                int n = nh + 2 * i;
                float4 av = *(const float4*)&attn_s[n * AST + m4 * 4];
                acc[i] = fmaf(av.x, v0, acc[i]);
                acc[i] = fmaf(av.y, v1, acc[i]);
                acc[i] = fmaf(av.z, v2v, acc[i]);
                acc[i] = fmaf(av.w, v3, acc[i]);
            }
        }
        {
            float v0 = V_s[48 * QST + d];
            float v1 = V_s[49 * QST + d];
#pragma unroll
            for (int i = 0; i < 25; i++) {
                int n = nh + 2 * i;
                acc[i] = fmaf(attn_s[n * AST + 48], v0, acc[i]);
                acc[i] = fmaf(attn_s[n * AST + 49], v1, acc[i]);
            }
        }
#pragma unroll
        for (int i = 0; i < 25; i++) {
            int n = nh + 2 * i;
            g_S[(b * NSEQ + n) * DD + d] = acc[i];
        }
    }
}

// ---------------- Kernel 2: bf16 tensor-core match GEMM + bias + softmax ----------
// grid = (8, B), block = 256 (8 warps), dyn smem = 81216 B
__global__ __launch_bounds__(256, 2)
void match_kernel(const int* __restrict__ poi_idx,
                  const float* __restrict__ lat, const float* __restrict__ lon,
                  const float* __restrict__ centroids,
                  const float* __restrict__ E_dm,
                  const float* __restrict__ region_emb,
                  float* __restrict__ out) {
    extern __shared__ float sm[];
    __nv_bfloat16* S_bf = (__nv_bfloat16*)sm;      // 64 x BST
    __nv_bfloat16* E_bf = S_bf + 64 * BST;         // 128 x BST
    float* ms_s  = (float*)(E_bf + 128 * BST);     // 50*132 = 6600
    float* lan   = ms_s + 50 * 132;                // 50
    float* lonn  = lan + 50;
    float* cn    = lonn + 50;
    float* pn    = cn + 50;
    float* lar   = pn + 50;                        // 128
    float* lor   = lar + 128;
    float* cr    = lor + 128;
    float* Edm_s = cr + 128;                       // 64

    int b = blockIdx.y;
    int r0 = blockIdx.x * 128;
    int tid = threadIdx.x;

    if (tid < 64) Edm_s[tid] = E_dm[tid];
    if (tid < NSEQ) {
        pn[tid] = (poi_idx[b * NSEQ + tid] < 0) ? 1.f : 0.f;
        float lt = lat[b * NSEQ + tid];
        lan[tid] = lt;
        lonn[tid] = lon[b * NSEQ + tid];
        cn[tid] = coslat(lt);
    }
    if (tid >= 64 && tid < 192) {
        int j = tid - 64;
        int r = r0 + j;
        float lt = 0.f, ln = 0.f;
        if (r < RCNT) { lt = centroids[2 * r]; ln = centroids[2 * r + 1]; }
        lar[j] = lt; lor[j] = ln; cr[j] = coslat(lt);
    }
    // S tile: 64 rows x 128 k (rows >= 50 zero), fp32 -> bf16
    for (int idx = tid; idx < 64 * 32; idx += 256) {
        int row = idx >> 5, c = idx & 31;
        float4 v = make_float4(0.f, 0.f, 0.f, 0.f);
        if (row < NSEQ) v = *(const float4*)&g_S[b * NSEQ * DD + row * DD + c * 4];
        __nv_bfloat162 p0 = __floats2bfloat162_rn(v.x, v.y);
        __nv_bfloat162 p1 = __floats2bfloat162_rn(v.z, v.w);
        *(__nv_bfloat162*)&S_bf[row * BST + c * 4]     = p0;
        *(__nv_bfloat162*)&S_bf[row * BST + c * 4 + 2] = p1;
    }
    // E tile: 128 rows(j) x 128 k, fp32 -> bf16
    for (int idx = tid; idx < 128 * 32; idx += 256) {
        int j = idx >> 5, c = idx & 31;
        int r = r0 + j;
        float4 v = make_float4(0.f, 0.f, 0.f, 0.f);
        if (r < RCNT) v = *(const float4*)&region_emb[r * DD + c * 4];
        __nv_bfloat162 p0 = __floats2bfloat162_rn(v.x, v.y);
        __nv_bfloat162 p1 = __floats2bfloat162_rn(v.z, v.w);
        *(__nv_bfloat162*)&E_bf[j * BST + c * 4]     = p0;
        *(__nv_bfloat162*)&E_bf[j * BST + c * 4 + 2] = p1;
    }
    __syncthreads();

    // MMA: warp grid 2(n) x 4(j); each warp 32x32 tile of C[n][j] = S @ E^T
    int warp = tid >> 5, lane = tid & 31;
    int nbase = (warp >> 2) * 32;
    int jbase = (warp & 3) * 32;

    float acc[2][4][4];
#pragma unroll
    for (int a = 0; a < 2; a++)
#pragma unroll
        for (int c = 0; c < 4; c++)
#pragma unroll
            for (int e = 0; e < 4; e++) acc[a][c][e] = 0.f;

    int arow = lane & 15, acol = (lane >> 4) << 3;
    int bj   = (lane & 7) | ((lane >> 4) << 3);
    int bk   = ((lane >> 3) & 1) << 3;
    uint32_t aAddr0 = smem_u32(&S_bf[(nbase + arow) * BST + acol]);
    uint32_t aAddr1 = smem_u32(&S_bf[(nbase + 16 + arow) * BST + acol]);
    uint32_t bAddr0 = smem_u32(&E_bf[(jbase + bj) * BST + bk]);
    uint32_t bAddr1 = smem_u32(&E_bf[(jbase + 16 + bj) * BST + bk]);

#pragma unroll
    for (int ks = 0; ks < 8; ks++) {
        uint32_t a0[4], a1[4], b0[4], b1[4];
        uint32_t koff = ks * 32;  // 16 bf16 = 32 bytes
        LDMX4(a0, aAddr0 + koff);
        LDMX4(a1, aAddr1 + koff);
        LDMX4(b0, bAddr0 + koff);
        LDMX4(b1, bAddr1 + koff);
        MMA16816(acc[0][0], a0, b0[0], b0[1]);
        MMA16816(acc[0][1], a0, b0[2], b0[3]);
        MMA16816(acc[0][2], a0, b1[0], b1[1]);
        MMA16816(acc[0][3], a0, b1[2], b1[3]);
        MMA16816(acc[1][0], a1, b0[0], b0[1]);
        MMA16816(acc[1][1], a1, b0[2], b0[3]);
        MMA16816(acc[1][2], a1, b1[0], b1[1]);
        MMA16816(acc[1][3], a1, b1[2], b1[3]);
    }

    // epilogue: bias + store m_scores
    int trow = lane >> 2, tcol = (lane & 3) << 1;
#pragma unroll
    for (int mi = 0; mi < 2; mi++) {
#pragma unroll
        for (int rh = 0; rh < 2; rh++) {
            int n = nbase + mi * 16 + trow + rh * 8;
            if (n < NSEQ) {
                float la_n = lan[n], lo_n = lonn[n], c_n = cn[n];
#pragma unroll
                for (int jt = 0; jt < 4; jt++) {
#pragma unroll
                    for (int e = 0; e < 2; e++) {
                        int j = jbase + jt * 8 + tcol + e;
                        float dd = hav_dist(la_n, lo_n, c_n, lar[j], lor[j], cr[j]);
                        float bias = interp64(Edm_s, dd * (63.f / 200.f));
                        ms_s[n * 132 + j] = acc[mi][jt][rh * 2 + e] * SCALE + bias;
                    }
                }
            }
        }
    }
    __syncthreads();

    // softmax over n per column + weighted score sum; 2 threads per column
    {
        int j = tid >> 1, half = tid & 1;
        bool active = (r0 + j) < RCNT;
        int n0 = half * 25;
        float mx = -1e38f;
        if (active) {
            for (int n = n0; n < n0 + 25; n++)
                if (pn[n] < 0.5f) mx = fmaxf(mx, ms_s[n * 132 + j]);
        }
        mx = fmaxf(mx, __shfl_xor_sync(0xffffffff, mx, 1));
        float sum = 0.f, accv = 0.f;
        if (active) {
            for (int n = n0; n < n0 + 25; n++) {
                if (pn[n] < 0.5f) {
                    float v = ms_s[n * 132 + j];
                    float e = __expf(v - mx);
                    sum += e;
                    accv += e * v;
                }
            }
        }
        sum  += __shfl_xor_sync(0xffffffff, sum, 1);
        accv += __shfl_xor_sync(0xffffffff, accv, 1);
        if (active && half == 0)
            out[b * RCNT + r0 + j] = (sum > 0.f) ? accv / sum : 0.f;
    }
}

extern "C" void kernel_launch(void* const* d_in, const int* in_sizes, int n_in,
                              void* d_out, int out_size) {
    const int*   poi_idx  = (const int*)d_in[0];
    const int*   hour     = (const int*)d_in[1];
    const float* lat      = (const float*)d_in[2];
    const float* lon      = (const float*)d_in[3];
    const float* t_min    = (const float*)d_in[4];
    const float* cent     = (const float*)d_in[5];
    const float* poi_emb  = (const float*)d_in[6];
    const float* time_emb = (const float*)d_in[7];
    const float* E_t      = (const float*)d_in[8];
    const float* E_d      = (const float*)d_in[9];
    const float* E_dm     = (const float*)d_in[10];
    const float* remb     = (const float*)d_in[11];
    const float* Wq       = (const float*)d_in[12];
    const float* Wk       = (const float*)d_in[13];
    const float* Wv       = (const float*)d_in[14];
    float* out = (float*)d_out;

    const int SMEM_A = 26928 * 4;   // 107712 B
    const int SMEM_B = 81216;       // bf16 tiles + scores + geo
    cudaFuncSetAttribute(attn_kernel,  cudaFuncAttributeMaxDynamicSharedMemorySize, SMEM_A);
    cudaFuncSetAttribute(match_kernel, cudaFuncAttributeMaxDynamicSharedMemorySize, SMEM_B);

    attn_kernel<<<BATCH, 256, SMEM_A>>>(poi_idx, hour, lat, lon, t_min,
                                        poi_emb, time_emb, E_t, E_d, Wq, Wk, Wv);
    match_kernel<<<dim3(8, BATCH), 256, SMEM_B>>>(poi_idx, lat, lon, cent,
                                                  E_dm, remb, out);
}

// round 9
// speedup vs baseline: 4.5021x; 2.2600x over previous
#include <cuda_runtime.h>
#include <cuda_bf16.h>
#include <cstdint>
#include <math.h>

#define BATCH   1024
#define NSEQ    50
#define RCNT    1000
#define NPOIS   50000
#define DD      128
#define BST     136   // bf16 MMA tile row stride (elements)
#define VST     72    // V_T / attn bf16 row stride (elements)
#define DEG2RAD 0.017453292519943295f
#define KHALF   0.008726646259971648f   // 0.5 * DEG2RAD
#define BINFOLD 4013.7299f              // 12742 * 63 / 200
#define SCALE   0.08838834764831845f    // 1/sqrt(128)

// scratch: S = attn @ V, (B, N, D) bf16
__device__ __align__(16) __nv_bfloat16 g_S_bf[BATCH * NSEQ * DD];

__device__ __forceinline__ float interp2(const float2* t, float x) {
    int k = (int)x;
    float f = x - (float)k;
    float2 v = t[k];
    return fmaf(f, v.y, v.x);
}

__device__ __forceinline__ float coslat(float latdeg) {
    float r = latdeg * DEG2RAD;
    float r2 = r * r;
    return 1.f - 0.5f * r2 + r2 * r2 * (1.f / 24.f);
}

__device__ __forceinline__ uint32_t smem_u32(const void* p) {
    return (uint32_t)__cvta_generic_to_shared(p);
}

#define LDMX4(R, addr)                                                        \
    asm volatile("ldmatrix.sync.aligned.m8n8.x4.shared.b16 {%0,%1,%2,%3}, [%4];" \
                 : "=r"((R)[0]), "=r"((R)[1]), "=r"((R)[2]), "=r"((R)[3])      \
                 : "r"(addr))

#define MMA16816(C, A, B0, B1)                                                \
    asm volatile("mma.sync.aligned.m16n8k16.row.col.f32.bf16.bf16.f32 "       \
                 "{%0,%1,%2,%3},{%4,%5,%6,%7},{%8,%9},{%0,%1,%2,%3};"         \
                 : "+f"((C)[0]), "+f"((C)[1]), "+f"((C)[2]), "+f"((C)[3])      \
                 : "r"((A)[0]), "r"((A)[1]), "r"((A)[2]), "r"((A)[3]),         \
                   "r"(B0), "r"(B1))

// ---------------- Kernel 1: gather + bf16-MMA QKV + biased attention -> S(bf16) ----
// grid = B, block = 256 (8 warps), dyn smem = 107776 B
__global__ __launch_bounds__(256, 2)
void attn_kernel(const int* __restrict__ poi_idx, const int* __restrict__ hour,
                 const float* __restrict__ lat, const float* __restrict__ lon,
                 const float* __restrict__ t_min,
                 const float* __restrict__ poi_emb, const float* __restrict__ time_emb,
                 const float* __restrict__ E_t, const float* __restrict__ E_d,
                 const float* __restrict__ Wq, const float* __restrict__ Wk,
                 const float* __restrict__ Wv) {
    extern __shared__ char smc[];
    __nv_bfloat16* x_bf  = (__nv_bfloat16*)(smc);            // 64 x 136 = 17408 B
    __nv_bfloat16* W_bf  = (__nv_bfloat16*)(smc + 17408);    // 128 x 136 = 34816 B
    __nv_bfloat16* Q_bf  = (__nv_bfloat16*)(smc + 52224);    // 64 x 136
    __nv_bfloat16* K_bf  = (__nv_bfloat16*)(smc + 69632);    // 64 x 136
    __nv_bfloat16* V_T   = (__nv_bfloat16*)(smc + 87040);    // 128 x 72 = 18432 B
    float* geo   = (float*)(smc + 105472);
    float* tv    = geo;            // 64
    float* yl    = geo + 64;
    float* xl    = geo + 128;
    float* cl    = geo + 192;
    float* padf  = geo + 256;
    float2* Et2  = (float2*)(geo + 320);   // 64 float2
    float2* Ed2  = (float2*)(geo + 448);   // 64 float2
    __nv_bfloat16* attn_bf = x_bf;          // alias, 64 x 72 (x dead by then)

    int b = blockIdx.x;
    int tid = threadIdx.x;
    int warp = tid >> 5, lane = tid & 31;

    if (tid < 64) {
        int t1 = (tid < 63) ? tid + 1 : 63;
        float e0 = E_t[tid];
        Et2[tid] = make_float2(e0, E_t[t1] - e0);
        float d0 = E_d[tid];
        Ed2[tid] = make_float2(d0, E_d[t1] - d0);
        if (tid < NSEQ) {
            int pi = poi_idx[b * NSEQ + tid];
            padf[tid] = (pi < 0) ? 1.f : 0.f;
            tv[tid] = t_min[b * NSEQ + tid];
            float lt = lat[b * NSEQ + tid];
            yl[tid] = lt * KHALF;
            xl[tid] = lon[b * NSEQ + tid] * KHALF;
            cl[tid] = coslat(lt);
        } else {
            padf[tid] = 1.f; tv[tid] = 0.f;
            yl[tid] = 0.f; xl[tid] = 0.f; cl[tid] = 1.f;
        }
    }
    // gather x = poi_emb + time_emb, bf16, rows >= 50 zero
    for (int idx = tid; idx < 64 * 64; idx += 256) {
        int row = idx >> 6, c2 = idx & 63;
        float2 v = make_float2(0.f, 0.f);
        if (row < NSEQ) {
            int pi = poi_idx[b * NSEQ + row];
            int ps, hs;
            if (pi < 0) { ps = NPOIS; hs = 0; }
            else        { ps = pi;    hs = hour[b * NSEQ + row]; }
            float2 p = *(const float2*)&poi_emb[ps * DD + c2 * 2];
            float2 t = *(const float2*)&time_emb[hs * DD + c2 * 2];
            v = make_float2(p.x + t.x, p.y + t.y);
        }
        *(__nv_bfloat162*)&x_bf[row * BST + c2 * 2] = __floats2bfloat162_rn(v.x, v.y);
    }

    // fragment geometry (shared by all MMA phases)
    int arow = lane & 15, acol = (lane >> 4) << 3;
    int bj   = (lane & 7) | ((lane >> 4) << 3);
    int bk   = ((lane >> 3) & 1) << 3;
    int trow = lane >> 2, tcol = (lane & 3) << 1;

    // ---- Phase B: QKV projections via MMA (loop over Wq, Wk, Wv) ----
    int nbase = (warp >> 2) * 32;
    int jbase = (warp & 3) * 32;
#pragma unroll 1
    for (int p = 0; p < 3; p++) {
        const float* W = (p == 0) ? Wq : (p == 1) ? Wk : Wv;
        for (int idx = tid; idx < 128 * 32; idx += 256) {
            int row = idx >> 5, c4 = idx & 31;
            float4 v = *(const float4*)&W[row * DD + c4 * 4];
            *(__nv_bfloat162*)&W_bf[row * BST + c4 * 4]     = __floats2bfloat162_rn(v.x, v.y);
            *(__nv_bfloat162*)&W_bf[row * BST + c4 * 4 + 2] = __floats2bfloat162_rn(v.z, v.w);
        }
        __syncthreads();

        float acc[2][4][4];
#pragma unroll
        for (int a = 0; a < 2; a++)
#pragma unroll
            for (int c = 0; c < 4; c++)
#pragma unroll
                for (int e = 0; e < 4; e++) acc[a][c][e] = 0.f;

        uint32_t aA0 = smem_u32(&x_bf[(nbase + arow) * BST + acol]);
        uint32_t aA1 = smem_u32(&x_bf[(nbase + 16 + arow) * BST + acol]);
        uint32_t bA0 = smem_u32(&W_bf[(jbase + bj) * BST + bk]);
        uint32_t bA1 = smem_u32(&W_bf[(jbase + 16 + bj) * BST + bk]);
#pragma unroll
        for (int ks = 0; ks < 8; ks++) {
            uint32_t a0[4], a1[4], b0[4], b1[4];
            uint32_t koff = ks * 32;
            LDMX4(a0, aA0 + koff);
            LDMX4(a1, aA1 + koff);
            LDMX4(b0, bA0 + koff);
            LDMX4(b1, bA1 + koff);
            MMA16816(acc[0][0], a0, b0[0], b0[1]);
            MMA16816(acc[0][1], a0, b0[2], b0[3]);
            MMA16816(acc[0][2], a0, b1[0], b1[1]);
            MMA16816(acc[0][3], a0, b1[2], b1[3]);
            MMA16816(acc[1][0], a1, b0[0], b0[1]);
            MMA16816(acc[1][1], a1, b0[2], b0[3]);
            MMA16816(acc[1][2], a1, b1[0], b1[1]);
            MMA16816(acc[1][3], a1, b1[2], b1[3]);
        }

        if (p < 2) {
            __nv_bfloat16* dst = (p == 0) ? Q_bf : K_bf;
#pragma unroll
            for (int mi = 0; mi < 2; mi++)
#pragma unroll
                for (int rh = 0; rh < 2; rh++) {
                    int n = nbase + mi * 16 + trow + rh * 8;
#pragma unroll
                    for (int jt = 0; jt < 4; jt++) {
                        int d0 = jbase + jt * 8 + tcol;
                        *(__nv_bfloat162*)&dst[n * BST + d0] =
                            __floats2bfloat162_rn(acc[mi][jt][rh * 2], acc[mi][jt][rh * 2 + 1]);
                    }
                }
        } else {
#pragma unroll
            for (int mi = 0; mi < 2; mi++)
#pragma unroll
                for (int rh = 0; rh < 2; rh++) {
                    int n = nbase + mi * 16 + trow + rh * 8;
#pragma unroll
                    for (int jt = 0; jt < 4; jt++)
#pragma unroll
                        for (int e = 0; e < 2; e++) {
                            int d = jbase + jt * 8 + tcol + e;
                            V_T[d * VST + n] = __float2bfloat16(acc[mi][jt][rh * 2 + e]);
                        }
                }
        }
        __syncthreads();
    }

    // ---- Phase C: QK^T + bias + row softmax -> attn_bf (warps 0-3) ----
    if (warp < 4) {
        int nb = warp * 16;
        uint32_t aA = smem_u32(&Q_bf[(nb + arow) * BST + acol]);
        uint32_t bA[4];
#pragma unroll
        for (int t = 0; t < 4; t++)
            bA[t] = smem_u32(&K_bf[(t * 16 + bj) * BST + bk]);

        float acc[8][4];
#pragma unroll
        for (int t = 0; t < 8; t++)
#pragma unroll
            for (int e = 0; e < 4; e++) acc[t][e] = 0.f;

#pragma unroll
        for (int ks = 0; ks < 8; ks++) {
            uint32_t a[4];
            uint32_t koff = ks * 32;
            LDMX4(a, aA + koff);
#pragma unroll
            for (int t = 0; t < 4; t++) {
                uint32_t bb[4];
                LDMX4(bb, bA[t] + koff);
                MMA16816(acc[2 * t],     a, bb[0], bb[1]);
                MMA16816(acc[2 * t + 1], a, bb[2], bb[3]);
            }
        }

        // per-row bias + softmax (two rows per thread: half=0 -> trow, half=1 -> trow+8)
#pragma unroll
        for (int half = 0; half < 2; half++) {
            int n = nb + trow + half * 8;
            float tv_n = tv[n], y_n = yl[n], x_n = xl[n], c_n = cl[n];
            float vpn = 1.f - padf[n];
            float s[16];
#pragma unroll
            for (int t = 0; t < 8; t++)
#pragma unroll
                for (int e = 0; e < 2; e++) {
                    int m = t * 8 + tcol + e;
                    float vp = vpn * (1.f - padf[m]);
                    float dt = fabsf(tv_n - tv[m]) * vp;
                    float xt = fminf(dt * (63.f / 10080.f), 62.999996f);
                    float hl = yl[m] - y_n, ho = xl[m] - x_n;
                    float a2 = fmaf(hl, hl, c_n * cl[m] * ho * ho);
                    float sq = sqrtf(a2);
                    float bb = BINFOLD * sq;
                    float bin = fmaf(bb, a2 * (1.f / 6.f), bb) * vp;
                    float bias = interp2(Et2, xt) + interp2(Ed2, bin);
                    float v = acc[t][half * 2 + e] * SCALE + bias;
                    if (padf[m] > 0.5f) v = -1e30f;
                    s[t * 2 + e] = v;
                }
            float mx = -1e30f;
#pragma unroll
            for (int i = 0; i < 16; i++) mx = fmaxf(mx, s[i]);
            mx = fmaxf(mx, __shfl_xor_sync(0xffffffff, mx, 1));
            mx = fmaxf(mx, __shfl_xor_sync(0xffffffff, mx, 2));
            float sum = 0.f;
            float ex[16];
#pragma unroll
            for (int i = 0; i < 16; i++) {
                ex[i] = (s[i] > -1e29f) ? __expf(s[i] - mx) : 0.f;
                sum += ex[i];
            }
            sum += __shfl_xor_sync(0xffffffff, sum, 1);
            sum += __shfl_xor_sync(0xffffffff, sum, 2);
            float inv = (sum > 0.f) ? 1.f / sum : 0.f;
#pragma unroll
            for (int t = 0; t < 8; t++)
#pragma unroll
                for (int e = 0; e < 2; e++) {
                    int m = t * 8 + tcol + e;
                    attn_bf[n * VST + m] = __float2bfloat16(ex[t * 2 + e] * inv);
                }
        }
    }
    __syncthreads();

    // ---- Phase D: S = attn @ V via MMA, store bf16 to gmem ----
    {
        int dbase = jbase;
        float acc[2][4][4];
#pragma unroll
        for (int a = 0; a < 2; a++)
#pragma unroll
            for (int c = 0; c < 4; c++)
#pragma unroll
                for (int e = 0; e < 4; e++) acc[a][c][e] = 0.f;

        uint32_t aA0 = smem_u32(&attn_bf[(nbase + arow) * VST + acol]);
        uint32_t aA1 = smem_u32(&attn_bf[(nbase + 16 + arow) * VST + acol]);
        uint32_t bA0 = smem_u32(&V_T[(dbase + bj) * VST + bk]);
        uint32_t bA1 = smem_u32(&V_T[(dbase + 16 + bj) * VST + bk]);
#pragma unroll
        for (int ks = 0; ks < 4; ks++) {
            uint32_t a0[4], a1[4], b0[4], b1[4];
            uint32_t koff = ks * 32;
            LDMX4(a0, aA0 + koff);
            LDMX4(a1, aA1 + koff);
            LDMX4(b0, bA0 + koff);
            LDMX4(b1, bA1 + koff);
            MMA16816(acc[0][0], a0, b0[0], b0[1]);
            MMA16816(acc[0][1], a0, b0[2], b0[3]);
            MMA16816(acc[0][2], a0, b1[0], b1[1]);
            MMA16816(acc[0][3], a0, b1[2], b1[3]);
            MMA16816(acc[1][0], a1, b0[0], b0[1]);
            MMA16816(acc[1][1], a1, b0[2], b0[3]);
            MMA16816(acc[1][2], a1, b1[0], b1[1]);
            MMA16816(acc[1][3], a1, b1[2], b1[3]);
        }
#pragma unroll
        for (int mi = 0; mi < 2; mi++)
#pragma unroll
            for (int rh = 0; rh < 2; rh++) {
                int n = nbase + mi * 16 + trow + rh * 8;
                if (n < NSEQ) {
#pragma unroll
                    for (int jt = 0; jt < 4; jt++) {
                        int d0 = dbase + jt * 8 + tcol;
                        *(__nv_bfloat162*)&g_S_bf[b * (NSEQ * DD) + n * DD + d0] =
                            __floats2bfloat162_rn(acc[mi][jt][rh * 2], acc[mi][jt][rh * 2 + 1]);
                    }
                }
            }
    }
}

// ---------------- Kernel 2: bf16 tensor-core match GEMM + bias + softmax ----------
// grid = (8, B), block = 256 (8 warps), dyn smem = 55296 B
__global__ __launch_bounds__(256, 3)
void match_kernel(const int* __restrict__ poi_idx,
                  const float* __restrict__ lat, const float* __restrict__ lon,
                  const float* __restrict__ centroids,
                  const float* __restrict__ E_dm,
                  const float* __restrict__ region_emb,
                  float* __restrict__ out) {
    extern __shared__ char smc[];
    __nv_bfloat16* S_bf = (__nv_bfloat16*)(smc);           // 64 x 136 = 17408 B
    __nv_bfloat16* E_bf = (__nv_bfloat16*)(smc + 17408);   // 128 x 136 = 34816 B
    float* ms_s = (float*)(smc + 17408);                   // alias: 50*132*4 = 26400 B
    float* geo  = (float*)(smc + 52224);
    float* yn   = geo;          // 64
    float* xn   = geo + 64;
    float* cn   = geo + 128;
    float* pn   = geo + 192;
    float* yr   = geo + 256;    // 128
    float* xr   = geo + 384;
    float* cr   = geo + 512;
    float2* Edm2 = (float2*)(geo + 640);   // 64 float2

    int b = blockIdx.y;
    int r0 = blockIdx.x * 128;
    int tid = threadIdx.x;

    if (tid < 64) {
        int t1 = (tid < 63) ? tid + 1 : 63;
        float e0 = E_dm[tid];
        Edm2[tid] = make_float2(e0, E_dm[t1] - e0);
        if (tid < NSEQ) {
            pn[tid] = (poi_idx[b * NSEQ + tid] < 0) ? 1.f : 0.f;
            float lt = lat[b * NSEQ + tid];
            yn[tid] = lt * KHALF;
            xn[tid] = lon[b * NSEQ + tid] * KHALF;
            cn[tid] = coslat(lt);
        }
    }
    if (tid >= 64 && tid < 192) {
        int j = tid - 64;
        int r = r0 + j;
        float lt = 0.f, ln = 0.f;
        if (r < RCNT) { lt = centroids[2 * r]; ln = centroids[2 * r + 1]; }
        yr[j] = lt * KHALF; xr[j] = ln * KHALF; cr[j] = coslat(lt);
    }
    // S tile: raw bf16 copy (rows >= 50 zero)
    for (int idx = tid; idx < 64 * 16; idx += 256) {
        int row = idx >> 4, c = idx & 15;
        uint4 v = make_uint4(0u, 0u, 0u, 0u);
        if (row < NSEQ)
            v = *(const uint4*)&g_S_bf[b * (NSEQ * DD) + row * DD + c * 8];
        *(uint4*)&S_bf[row * BST + c * 8] = v;
    }
    // E tile: fp32 -> bf16
    for (int idx = tid; idx < 128 * 32; idx += 256) {
        int j = idx >> 5, c = idx & 31;
        int r = r0 + j;
        float4 v = make_float4(0.f, 0.f, 0.f, 0.f);
        if (r < RCNT) v = *(const float4*)&region_emb[r * DD + c * 4];
        *(__nv_bfloat162*)&E_bf[j * BST + c * 4]     = __floats2bfloat162_rn(v.x, v.y);
        *(__nv_bfloat162*)&E_bf[j * BST + c * 4 + 2] = __floats2bfloat162_rn(v.z, v.w);
    }
    __syncthreads();

    // MMA: warp grid 2(n) x 4(j)
    int warp = tid >> 5, lane = tid & 31;
    int nbase = (warp >> 2) * 32;
    int jbase = (warp & 3) * 32;

    float acc[2][4][4];
#pragma unroll
    for (int a = 0; a < 2; a++)
#pragma unroll
        for (int c = 0; c < 4; c++)
#pragma unroll
            for (int e = 0; e < 4; e++) acc[a][c][e] = 0.f;

    int arow = lane & 15, acol = (lane >> 4) << 3;
    int bj   = (lane & 7) | ((lane >> 4) << 3);
    int bk   = ((lane >> 3) & 1) << 3;
    uint32_t aAddr0 = smem_u32(&S_bf[(nbase + arow) * BST + acol]);
    uint32_t aAddr1 = smem_u32(&S_bf[(nbase + 16 + arow) * BST + acol]);
    uint32_t bAddr0 = smem_u32(&E_bf[(jbase + bj) * BST + bk]);
    uint32_t bAddr1 = smem_u32(&E_bf[(jbase + 16 + bj) * BST + bk]);

#pragma unroll
    for (int ks = 0; ks < 8; ks++) {
        uint32_t a0[4], a1[4], b0[4], b1[4];
        uint32_t koff = ks * 32;
        LDMX4(a0, aAddr0 + koff);
        LDMX4(a1, aAddr1 + koff);
        LDMX4(b0, bAddr0 + koff);
        LDMX4(b1, bAddr1 + koff);
        MMA16816(acc[0][0], a0, b0[0], b0[1]);
        MMA16816(acc[0][1], a0, b0[2], b0[3]);
        MMA16816(acc[0][2], a0, b1[0], b1[1]);
        MMA16816(acc[0][3], a0, b1[2], b1[3]);
        MMA16816(acc[1][0], a1, b0[0], b0[1]);
        MMA16816(acc[1][1], a1, b0[2], b0[3]);
        MMA16816(acc[1][2], a1, b1[0], b1[1]);
        MMA16816(acc[1][3], a1, b1[2], b1[3]);
    }
    __syncthreads();   // all warps done reading E_bf before ms_s overwrites it

    // epilogue: bias + store m_scores (ms_s aliases E_bf)
    int trow = lane >> 2, tcol = (lane & 3) << 1;
#pragma unroll
    for (int mi = 0; mi < 2; mi++) {
#pragma unroll
        for (int rh = 0; rh < 2; rh++) {
            int n = nbase + mi * 16 + trow + rh * 8;
            if (n < NSEQ) {
                float y_n = yn[n], x_n = xn[n], c_n = cn[n];
#pragma unroll
                for (int jt = 0; jt < 4; jt++) {
#pragma unroll
                    for (int e = 0; e < 2; e++) {
                        int j = jbase + jt * 8 + tcol + e;
                        float dy = y_n - yr[j], dx = x_n - xr[j];
                        float a2 = fmaf(dy, dy, c_n * cr[j] * dx * dx);
                        float sq = sqrtf(a2);
                        float bb = BINFOLD * sq;
                        float bin = fmaf(bb, a2 * (1.f / 6.f), bb);
                        float bias = interp2(Edm2, bin);
                        ms_s[n * 132 + j] = acc[mi][jt][rh * 2 + e] * SCALE + bias;
                    }
                }
            }
        }
    }
    __syncthreads();

    // softmax over n per column + weighted score sum; 2 threads per column
    {
        int j = tid >> 1, half = tid & 1;
        bool active = (r0 + j) < RCNT;
        int n0 = half * 25;
        float mx = -1e38f;
        if (active) {
            for (int n = n0; n < n0 + 25; n++)
                if (pn[n] < 0.5f) mx = fmaxf(mx, ms_s[n * 132 + j]);
        }
        mx = fmaxf(mx, __shfl_xor_sync(0xffffffff, mx, 1));
        float sum = 0.f, accv = 0.f;
        if (active) {
            for (int n = n0; n < n0 + 25; n++) {
                if (pn[n] < 0.5f) {
                    float v = ms_s[n * 132 + j];
                    float e = __expf(v - mx);
                    sum += e;
                    accv += e * v;
                }
            }
        }
        sum  += __shfl_xor_sync(0xffffffff, sum, 1);
        accv += __shfl_xor_sync(0xffffffff, accv, 1);
        if (active && half == 0)
            out[b * RCNT + r0 + j] = (sum > 0.f) ? accv / sum : 0.f;
    }
}

extern "C" void kernel_launch(void* const* d_in, const int* in_sizes, int n_in,
                              void* d_out, int out_size) {
    const int*   poi_idx  = (const int*)d_in[0];
    const int*   hour     = (const int*)d_in[1];
    const float* lat      = (const float*)d_in[2];
    const float* lon      = (const float*)d_in[3];
    const float* t_min    = (const float*)d_in[4];
    const float* cent     = (const float*)d_in[5];
    const float* poi_emb  = (const float*)d_in[6];
    const float* time_emb = (const float*)d_in[7];
    const float* E_t      = (const float*)d_in[8];
    const float* E_d      = (const float*)d_in[9];
    const float* E_dm     = (const float*)d_in[10];
    const float* remb     = (const float*)d_in[11];
    const float* Wq       = (const float*)d_in[12];
    const float* Wk       = (const float*)d_in[13];
    const float* Wv       = (const float*)d_in[14];
    float* out = (float*)d_out;

    const int SMEM_A = 107776;
    const int SMEM_B = 55296;
    cudaFuncSetAttribute(attn_kernel,  cudaFuncAttributeMaxDynamicSharedMemorySize, SMEM_A);
    cudaFuncSetAttribute(match_kernel, cudaFuncAttributeMaxDynamicSharedMemorySize, SMEM_B);

    attn_kernel<<<BATCH, 256, SMEM_A>>>(poi_idx, hour, lat, lon, t_min,
                                        poi_emb, time_emb, E_t, E_d, Wq, Wk, Wv);
    match_kernel<<<dim3(8, BATCH), 256, SMEM_B>>>(poi_idx, lat, lon, cent,
                                                  E_dm, remb, out);
}

// round 12
// speedup vs baseline: 5.7008x; 1.2662x over previous
#include <cuda_runtime.h>
#include <cuda_bf16.h>
#include <cstdint>
#include <math.h>

#define BATCH   1024
#define NSEQ    50
#define RCNT    1000
#define NPOIS   50000
#define DD      128
#define BST     136   // bf16 MMA tile row stride (elements)
#define VST     72    // V_T / attn bf16 row stride (elements)
#define DEG2RAD 0.017453292519943295f
#define KHALF   0.008726646259971648f   // 0.5 * DEG2RAD
#define BINFOLD 4013.7299f              // 12742 * 63 / 200
#define SCALE   0.08838834764831845f    // 1/sqrt(128)

// scratch: S = attn @ V (pre-scaled by 1/sqrt(D)), (B, N, D) bf16
__device__ __align__(16) __nv_bfloat16 g_S_bf[BATCH * NSEQ * DD];
// region_emb pre-converted to bf16, zero-padded to 1024 rows
__device__ __align__(16) __nv_bfloat16 g_E_bf[1024 * DD];

__device__ __forceinline__ float interp2(const float2* t, float x) {
    int k = (int)x;
    float f = x - (float)k;
    float2 v = t[k];
    return fmaf(f, v.y, v.x);
}

__device__ __forceinline__ float coslat(float latdeg) {
    float r = latdeg * DEG2RAD;
    float r2 = r * r;
    return 1.f - 0.5f * r2 + r2 * r2 * (1.f / 24.f);
}

__device__ __forceinline__ uint32_t smem_u32(const void* p) {
    return (uint32_t)__cvta_generic_to_shared(p);
}

#define LDMX4(R, addr)                                                        \
    asm volatile("ldmatrix.sync.aligned.m8n8.x4.shared.b16 {%0,%1,%2,%3}, [%4];" \
                 : "=r"((R)[0]), "=r"((R)[1]), "=r"((R)[2]), "=r"((R)[3])      \
                 : "r"(addr))

#define MMA16816(C, A, B0, B1)                                                \
    asm volatile("mma.sync.aligned.m16n8k16.row.col.f32.bf16.bf16.f32 "       \
                 "{%0,%1,%2,%3},{%4,%5,%6,%7},{%8,%9},{%0,%1,%2,%3};"         \
                 : "+f"((C)[0]), "+f"((C)[1]), "+f"((C)[2]), "+f"((C)[3])      \
                 : "r"((A)[0]), "r"((A)[1]), "r"((A)[2]), "r"((A)[3]),         \
                   "r"(B0), "r"(B1))

// ---------------- Kernel 0: convert region_emb -> bf16 (zero-padded) ----------
__global__ void conv_E_kernel(const float* __restrict__ remb) {
    int idx = blockIdx.x * 256 + threadIdx.x;   // float2 index, 65536 total
    int r = idx >> 6;
    float2 v = make_float2(0.f, 0.f);
    if (r < RCNT) v = ((const float2*)remb)[idx];
    *(__nv_bfloat162*)&g_E_bf[idx * 2] = __floats2bfloat162_rn(v.x, v.y);
}

// ---------------- Kernel 1: gather + bf16-MMA QKV + biased attention -> S(bf16) ----
// grid = B, block = 256 (8 warps), dyn smem = 107776 B
__global__ __launch_bounds__(256, 2)
void attn_kernel(const int* __restrict__ poi_idx, const int* __restrict__ hour,
                 const float* __restrict__ lat, const float* __restrict__ lon,
                 const float* __restrict__ t_min,
                 const float* __restrict__ poi_emb, const float* __restrict__ time_emb,
                 const float* __restrict__ E_t, const float* __restrict__ E_d,
                 const float* __restrict__ Wq, const float* __restrict__ Wk,
                 const float* __restrict__ Wv) {
    extern __shared__ char smc[];
    __nv_bfloat16* x_bf  = (__nv_bfloat16*)(smc);            // 64 x 136 = 17408 B
    __nv_bfloat16* W_bf  = (__nv_bfloat16*)(smc + 17408);    // 128 x 136 = 34816 B
    __nv_bfloat16* Q_bf  = (__nv_bfloat16*)(smc + 52224);    // 64 x 136
    __nv_bfloat16* K_bf  = (__nv_bfloat16*)(smc + 69632);    // 64 x 136
    __nv_bfloat16* V_T   = (__nv_bfloat16*)(smc + 87040);    // 128 x 72 = 18432 B
    float* geo   = (float*)(smc + 105472);
    float* tv    = geo;            // 64
    float* yl    = geo + 64;
    float* xl    = geo + 128;
    float* cl    = geo + 192;
    float* padf  = geo + 256;
    float2* Et2  = (float2*)(geo + 320);   // 64 float2
    float2* Ed2  = (float2*)(geo + 448);   // 64 float2
    __nv_bfloat16* attn_bf = x_bf;          // alias, 64 x 72 (x dead by then)

    int b = blockIdx.x;
    int tid = threadIdx.x;
    int warp = tid >> 5, lane = tid & 31;

    if (tid < 64) {
        int t1 = (tid < 63) ? tid + 1 : 63;
        float e0 = E_t[tid];
        Et2[tid] = make_float2(e0, E_t[t1] - e0);
        float d0 = E_d[tid];
        Ed2[tid] = make_float2(d0, E_d[t1] - d0);
        if (tid < NSEQ) {
            int pi = poi_idx[b * NSEQ + tid];
            padf[tid] = (pi < 0) ? 1.f : 0.f;
            tv[tid] = t_min[b * NSEQ + tid];
            float lt = lat[b * NSEQ + tid];
            yl[tid] = lt * KHALF;
            xl[tid] = lon[b * NSEQ + tid] * KHALF;
            cl[tid] = coslat(lt);
        } else {
            padf[tid] = 1.f; tv[tid] = 0.f;
            yl[tid] = 0.f; xl[tid] = 0.f; cl[tid] = 1.f;
        }
    }
    // gather x = poi_emb + time_emb, bf16, rows >= 50 zero
    for (int idx = tid; idx < 64 * 64; idx += 256) {
        int row = idx >> 6, c2 = idx & 63;
        float2 v = make_float2(0.f, 0.f);
        if (row < NSEQ) {
            int pi = poi_idx[b * NSEQ + row];
            int ps, hs;
            if (pi < 0) { ps = NPOIS; hs = 0; }
            else        { ps = pi;    hs = hour[b * NSEQ + row]; }
            float2 p = *(const float2*)&poi_emb[ps * DD + c2 * 2];
            float2 t = *(const float2*)&time_emb[hs * DD + c2 * 2];
            v = make_float2(p.x + t.x, p.y + t.y);
        }
        *(__nv_bfloat162*)&x_bf[row * BST + c2 * 2] = __floats2bfloat162_rn(v.x, v.y);
    }

    // fragment geometry (shared by all MMA phases)
    int arow = lane & 15, acol = (lane >> 4) << 3;
    int bj   = (lane & 7) | ((lane >> 4) << 3);
    int bk   = ((lane >> 3) & 1) << 3;
    int trow = lane >> 2, tcol = (lane & 3) << 1;

    // ---- Phase B: QKV projections via MMA (loop over Wq, Wk, Wv) ----
    int nbase = (warp >> 2) * 32;
    int jbase = (warp & 3) * 32;
#pragma unroll 1
    for (int p = 0; p < 3; p++) {
        const float* W = (p == 0) ? Wq : (p == 1) ? Wk : Wv;
        for (int idx = tid; idx < 128 * 32; idx += 256) {
            int row = idx >> 5, c4 = idx & 31;
            float4 v = *(const float4*)&W[row * DD + c4 * 4];
            *(__nv_bfloat162*)&W_bf[row * BST + c4 * 4]     = __floats2bfloat162_rn(v.x, v.y);
            *(__nv_bfloat162*)&W_bf[row * BST + c4 * 4 + 2] = __floats2bfloat162_rn(v.z, v.w);
        }
        __syncthreads();

        float acc[2][4][4];
#pragma unroll
        for (int a = 0; a < 2; a++)
#pragma unroll
            for (int c = 0; c < 4; c++)
#pragma unroll
                for (int e = 0; e < 4; e++) acc[a][c][e] = 0.f;

        uint32_t aA0 = smem_u32(&x_bf[(nbase + arow) * BST + acol]);
        uint32_t aA1 = smem_u32(&x_bf[(nbase + 16 + arow) * BST + acol]);
        uint32_t bA0 = smem_u32(&W_bf[(jbase + bj) * BST + bk]);
        uint32_t bA1 = smem_u32(&W_bf[(jbase + 16 + bj) * BST + bk]);
#pragma unroll
        for (int ks = 0; ks < 8; ks++) {
            uint32_t a0[4], a1[4], b0[4], b1[4];
            uint32_t koff = ks * 32;
            LDMX4(a0, aA0 + koff);
            LDMX4(a1, aA1 + koff);
            LDMX4(b0, bA0 + koff);
            LDMX4(b1, bA1 + koff);
            MMA16816(acc[0][0], a0, b0[0], b0[1]);
            MMA16816(acc[0][1], a0, b0[2], b0[3]);
            MMA16816(acc[0][2], a0, b1[0], b1[1]);
            MMA16816(acc[0][3], a0, b1[2], b1[3]);
            MMA16816(acc[1][0], a1, b0[0], b0[1]);
            MMA16816(acc[1][1], a1, b0[2], b0[3]);
            MMA16816(acc[1][2], a1, b1[0], b1[1]);
            MMA16816(acc[1][3], a1, b1[2], b1[3]);
        }

        if (p < 2) {
            __nv_bfloat16* dst = (p == 0) ? Q_bf : K_bf;
#pragma unroll
            for (int mi = 0; mi < 2; mi++)
#pragma unroll
                for (int rh = 0; rh < 2; rh++) {
                    int n = nbase + mi * 16 + trow + rh * 8;
#pragma unroll
                    for (int jt = 0; jt < 4; jt++) {
                        int d0 = jbase + jt * 8 + tcol;
                        *(__nv_bfloat162*)&dst[n * BST + d0] =
                            __floats2bfloat162_rn(acc[mi][jt][rh * 2], acc[mi][jt][rh * 2 + 1]);
                    }
                }
        } else {
#pragma unroll
            for (int mi = 0; mi < 2; mi++)
#pragma unroll
                for (int rh = 0; rh < 2; rh++) {
                    int n = nbase + mi * 16 + trow + rh * 8;
#pragma unroll
                    for (int jt = 0; jt < 4; jt++)
#pragma unroll
                        for (int e = 0; e < 2; e++) {
                            int d = jbase + jt * 8 + tcol + e;
                            V_T[d * VST + n] = __float2bfloat16(acc[mi][jt][rh * 2 + e]);
                        }
                }
        }
        __syncthreads();
    }

    // ---- Phase C: QK^T + bias + row softmax -> attn_bf (warps 0-3) ----
    if (warp < 4) {
        int nb = warp * 16;
        uint32_t aA = smem_u32(&Q_bf[(nb + arow) * BST + acol]);
        uint32_t bA[4];
#pragma unroll
        for (int t = 0; t < 4; t++)
            bA[t] = smem_u32(&K_bf[(t * 16 + bj) * BST + bk]);

        float acc[8][4];
#pragma unroll
        for (int t = 0; t < 8; t++)
#pragma unroll
            for (int e = 0; e < 4; e++) acc[t][e] = 0.f;

#pragma unroll
        for (int ks = 0; ks < 8; ks++) {
            uint32_t a[4];
            uint32_t koff = ks * 32;
            LDMX4(a, aA + koff);
#pragma unroll
            for (int t = 0; t < 4; t++) {
                uint32_t bb[4];
                LDMX4(bb, bA[t] + koff);
                MMA16816(acc[2 * t],     a, bb[0], bb[1]);
                MMA16816(acc[2 * t + 1], a, bb[2], bb[3]);
            }
        }

        // per-row bias + softmax (two rows per thread)
#pragma unroll
        for (int half = 0; half < 2; half++) {
            int n = nb + trow + half * 8;
            float tv_n = tv[n], y_n = yl[n], x_n = xl[n], c_n = cl[n];
            float vpn = 1.f - padf[n];
            float s[16];
#pragma unroll
            for (int t = 0; t < 8; t++)
#pragma unroll
                for (int e = 0; e < 2; e++) {
                    int m = t * 8 + tcol + e;
                    float vp = vpn * (1.f - padf[m]);
                    float dt = fabsf(tv_n - tv[m]) * vp;
                    float xt = fminf(dt * (63.f / 10080.f), 62.999996f);
                    float hl = yl[m] - y_n, ho = xl[m] - x_n;
                    float a2 = fmaf(hl, hl, c_n * cl[m] * ho * ho);
                    float sq = sqrtf(a2);
                    float bb = BINFOLD * sq;
                    float bin = fmaf(bb, a2 * (1.f / 6.f), bb) * vp;
                    float bias = interp2(Et2, xt) + interp2(Ed2, bin);
                    float v = acc[t][half * 2 + e] * SCALE + bias;
                    if (padf[m] > 0.5f) v = -1e30f;
                    s[t * 2 + e] = v;
                }
            float mx = -1e30f;
#pragma unroll
            for (int i = 0; i < 16; i++) mx = fmaxf(mx, s[i]);
            mx = fmaxf(mx, __shfl_xor_sync(0xffffffff, mx, 1));
            mx = fmaxf(mx, __shfl_xor_sync(0xffffffff, mx, 2));
            float sum = 0.f;
            float ex[16];
#pragma unroll
            for (int i = 0; i < 16; i++) {
                ex[i] = (s[i] > -1e29f) ? __expf(s[i] - mx) : 0.f;
                sum += ex[i];
            }
            sum += __shfl_xor_sync(0xffffffff, sum, 1);
            sum += __shfl_xor_sync(0xffffffff, sum, 2);
            float inv = (sum > 0.f) ? 1.f / sum : 0.f;
#pragma unroll
            for (int t = 0; t < 8; t++)
#pragma unroll
                for (int e = 0; e < 2; e++) {
                    int m = t * 8 + tcol + e;
                    attn_bf[n * VST + m] = __float2bfloat16(ex[t * 2 + e] * inv);
                }
        }
    }
    __syncthreads();

    // ---- Phase D: S = (attn @ V) * SCALE via MMA, store bf16 to gmem ----
    {
        int dbase = jbase;
        float acc[2][4][4];
#pragma unroll
        for (int a = 0; a < 2; a++)
#pragma unroll
            for (int c = 0; c < 4; c++)
#pragma unroll
                for (int e = 0; e < 4; e++) acc[a][c][e] = 0.f;

        uint32_t aA0 = smem_u32(&attn_bf[(nbase + arow) * VST + acol]);
        uint32_t aA1 = smem_u32(&attn_bf[(nbase + 16 + arow) * VST + acol]);
        uint32_t bA0 = smem_u32(&V_T[(dbase + bj) * VST + bk]);
        uint32_t bA1 = smem_u32(&V_T[(dbase + 16 + bj) * VST + bk]);
#pragma unroll
        for (int ks = 0; ks < 4; ks++) {
            uint32_t a0[4], a1[4], b0[4], b1[4];
            uint32_t koff = ks * 32;
            LDMX4(a0, aA0 + koff);
            LDMX4(a1, aA1 + koff);
            LDMX4(b0, bA0 + koff);
            LDMX4(b1, bA1 + koff);
            MMA16816(acc[0][0], a0, b0[0], b0[1]);
            MMA16816(acc[0][1], a0, b0[2], b0[3]);
            MMA16816(acc[0][2], a0, b1[0], b1[1]);
            MMA16816(acc[0][3], a0, b1[2], b1[3]);
            MMA16816(acc[1][0], a1, b0[0], b0[1]);
            MMA16816(acc[1][1], a1, b0[2], b0[3]);
            MMA16816(acc[1][2], a1, b1[0], b1[1]);
            MMA16816(acc[1][3], a1, b1[2], b1[3]);
        }
#pragma unroll
        for (int mi = 0; mi < 2; mi++)
#pragma unroll
            for (int rh = 0; rh < 2; rh++) {
                int n = nbase + mi * 16 + trow + rh * 8;
                if (n < NSEQ) {
#pragma unroll
                    for (int jt = 0; jt < 4; jt++) {
                        int d0 = dbase + jt * 8 + tcol;
                        *(__nv_bfloat162*)&g_S_bf[b * (NSEQ * DD) + n * DD + d0] =
                            __floats2bfloat162_rn(acc[mi][jt][rh * 2] * SCALE,
                                                  acc[mi][jt][rh * 2 + 1] * SCALE);
                    }
                }
            }
    }
}

// ---------------- Kernel 2: bf16 MMA match GEMM + bias + register softmax ----------
// grid = (8, B), block = 256 (8 warps), dyn smem = 55296 B
__global__ __launch_bounds__(256, 4)
void match_kernel(const int* __restrict__ poi_idx,
                  const float* __restrict__ lat, const float* __restrict__ lon,
                  const float* __restrict__ centroids,
                  const float* __restrict__ E_dm,
                  float* __restrict__ out) {
    extern __shared__ char smc[];
    __nv_bfloat16* S_bf = (__nv_bfloat16*)(smc);           // 64 x 136 = 17408 B
    // reduction arrays alias S_bf (dead after MMA phase)
    float* colmax = (float*)(smc);            // [2][128]
    float* sums   = (float*)(smc + 1024);     // [2][128]
    float* accvs  = (float*)(smc + 2048);     // [2][128]
    __nv_bfloat16* E_bf = (__nv_bfloat16*)(smc + 17408);   // 128 x 136 = 34816 B
    float* geo  = (float*)(smc + 52224);                   // 768 floats = 3072 B
    float* yn   = geo;          // 64
    float* xn   = geo + 64;
    float* cn   = geo + 128;
    float* pn   = geo + 192;
    float* yr   = geo + 256;    // 128
    float* xr   = geo + 384;
    float* cr   = geo + 512;
    float2* Edm2 = (float2*)(geo + 640);   // 64 float2

    int b = blockIdx.y;
    int r0 = blockIdx.x * 128;
    int tid = threadIdx.x;

    if (tid < 64) {
        int t1 = (tid < 63) ? tid + 1 : 63;
        float e0 = E_dm[tid];
        Edm2[tid] = make_float2(e0, E_dm[t1] - e0);
        if (tid < NSEQ) {
            pn[tid] = (poi_idx[b * NSEQ + tid] < 0) ? 1.f : 0.f;
            float lt = lat[b * NSEQ + tid];
            yn[tid] = lt * KHALF;
            xn[tid] = lon[b * NSEQ + tid] * KHALF;
            cn[tid] = coslat(lt);
        } else {
            pn[tid] = 1.f; yn[tid] = 0.f; xn[tid] = 0.f; cn[tid] = 1.f;
        }
    }
    if (tid >= 64 && tid < 192) {
        int j = tid - 64;
        int r = r0 + j;
        float lt = 0.f, ln = 0.f;
        if (r < RCNT) { lt = centroids[2 * r]; ln = centroids[2 * r + 1]; }
        yr[j] = lt * KHALF; xr[j] = ln * KHALF; cr[j] = coslat(lt);
    }
    // S tile: raw bf16 copy (rows >= 50 zero)
    for (int idx = tid; idx < 64 * 16; idx += 256) {
        int row = idx >> 4, c = idx & 15;
        uint4 v = make_uint4(0u, 0u, 0u, 0u);
        if (row < NSEQ)
            v = *(const uint4*)&g_S_bf[b * (NSEQ * DD) + row * DD + c * 8];
        *(uint4*)&S_bf[row * BST + c * 8] = v;
    }
    // E tile: raw bf16 copy from pre-converted g_E_bf (zero-padded rows)
    for (int idx = tid; idx < 128 * 16; idx += 256) {
        int row = idx >> 4, c = idx & 15;
        uint4 v = *(const uint4*)&g_E_bf[(r0 + row) * DD + c * 8];
        *(uint4*)&E_bf[row * BST + c * 8] = v;
    }
    __syncthreads();

    // MMA: warp grid 2(n) x 4(j)
    int warp = tid >> 5, lane = tid & 31;
    int wr = warp >> 2;            // warp row (n-half)
    int nbase = wr * 32;
    int jbase = (warp & 3) * 32;

    float acc[2][4][4];
#pragma unroll
    for (int a = 0; a < 2; a++)
#pragma unroll
        for (int c = 0; c < 4; c++)
#pragma unroll
            for (int e = 0; e < 4; e++) acc[a][c][e] = 0.f;

    int arow = lane & 15, acol = (lane >> 4) << 3;
    int bj   = (lane & 7) | ((lane >> 4) << 3);
    int bk   = ((lane >> 3) & 1) << 3;
    uint32_t aAddr0 = smem_u32(&S_bf[(nbase + arow) * BST + acol]);
    uint32_t aAddr1 = smem_u32(&S_bf[(nbase + 16 + arow) * BST + acol]);
    uint32_t bAddr0 = smem_u32(&E_bf[(jbase + bj) * BST + bk]);
    uint32_t bAddr1 = smem_u32(&E_bf[(jbase + 16 + bj) * BST + bk]);

#pragma unroll
    for (int ks = 0; ks < 8; ks++) {
        uint32_t a0[4], a1[4], b0[4], b1[4];
        uint32_t koff = ks * 32;
        LDMX4(a0, aAddr0 + koff);
        LDMX4(a1, aAddr1 + koff);
        LDMX4(b0, bAddr0 + koff);
        LDMX4(b1, bAddr1 + koff);
        MMA16816(acc[0][0], a0, b0[0], b0[1]);
        MMA16816(acc[0][1], a0, b0[2], b0[3]);
        MMA16816(acc[0][2], a0, b1[0], b1[1]);
        MMA16816(acc[0][3], a0, b1[2], b1[3]);
        MMA16816(acc[1][0], a1, b0[0], b0[1]);
        MMA16816(acc[1][1], a1, b0[2], b0[3]);
        MMA16816(acc[1][2], a1, b1[0], b1[1]);
        MMA16816(acc[1][3], a1, b1[2], b1[3]);
    }
    __syncthreads();   // S_bf dead; reduction arrays may now be written

    // ---- scores into registers: acc += bias (pad rows -> -1e30) ----
    int trow = lane >> 2, tcol = (lane & 3) << 1;
#pragma unroll
    for (int mi = 0; mi < 2; mi++) {
#pragma unroll
        for (int rh = 0; rh < 2; rh++) {
            int n = nbase + mi * 16 + trow + rh * 8;
            float y_n = yn[n], x_n = xn[n], c_n = cn[n];
            bool pad = pn[n] > 0.5f;
#pragma unroll
            for (int jt = 0; jt < 4; jt++) {
#pragma unroll
                for (int e = 0; e < 2; e++) {
                    int j = jbase + jt * 8 + tcol + e;
                    float dy = y_n - yr[j], dx = x_n - xr[j];
                    float a2 = fmaf(dy, dy, c_n * cr[j] * dx * dx);
                    float sq = sqrtf(a2);
                    float bb = BINFOLD * sq;
                    float bin = fmaf(bb, a2 * (1.f / 6.f), bb);
                    float v = acc[mi][jt][rh * 2 + e] + interp2(Edm2, bin);
                    acc[mi][jt][rh * 2 + e] = pad ? -1e30f : v;
                }
            }
        }
    }

    // ---- column max over this warp's 32 rows (reduce over trow lanes) ----
    float mx[8];
#pragma unroll
    for (int jt = 0; jt < 4; jt++)
#pragma unroll
        for (int e = 0; e < 2; e++) {
            float m = fmaxf(fmaxf(acc[0][jt][e], acc[0][jt][2 + e]),
                            fmaxf(acc[1][jt][e], acc[1][jt][2 + e]));
            m = fmaxf(m, __shfl_xor_sync(0xffffffff, m, 4));
            m = fmaxf(m, __shfl_xor_sync(0xffffffff, m, 8));
            m = fmaxf(m, __shfl_xor_sync(0xffffffff, m, 16));
            mx[jt * 2 + e] = m;
        }
    if (lane < 4) {
#pragma unroll
        for (int jt = 0; jt < 4; jt++)
#pragma unroll
            for (int e = 0; e < 2; e++)
                colmax[wr * 128 + jbase + jt * 8 + (lane << 1) + e] = mx[jt * 2 + e];
    }
    __syncthreads();

    // ---- global column max, then e/sum/accv with global max ----
#pragma unroll
    for (int jt = 0; jt < 4; jt++)
#pragma unroll
        for (int e = 0; e < 2; e++) {
            int j = jbase + jt * 8 + tcol + e;
            mx[jt * 2 + e] = fmaxf(colmax[j], colmax[128 + j]);
        }
    float sm[8], av[8];
#pragma unroll
    for (int i = 0; i < 8; i++) { sm[i] = 0.f; av[i] = 0.f; }
#pragma unroll
    for (int mi = 0; mi < 2; mi++)
#pragma unroll
        for (int jt = 0; jt < 4; jt++)
#pragma unroll
            for (int q = 0; q < 4; q++) {
                int e = q & 1;
                float v = acc[mi][jt][q];
                float ex = (v > -1e29f) ? __expf(v - mx[jt * 2 + e]) : 0.f;
                sm[jt * 2 + e] += ex;
                av[jt * 2 + e] += ex * v;
            }
#pragma unroll
    for (int i = 0; i < 8; i++) {
        sm[i] += __shfl_xor_sync(0xffffffff, sm[i], 4);
        sm[i] += __shfl_xor_sync(0xffffffff, sm[i], 8);
        sm[i] += __shfl_xor_sync(0xffffffff, sm[i], 16);
        av[i] += __shfl_xor_sync(0xffffffff, av[i], 4);
        av[i] += __shfl_xor_sync(0xffffffff, av[i], 8);
        av[i] += __shfl_xor_sync(0xffffffff, av[i], 16);
    }
    if (lane < 4) {
#pragma unroll
        for (int jt = 0; jt < 4; jt++)
#pragma unroll
            for (int e = 0; e < 2; e++) {
                int j = jbase + jt * 8 + (lane << 1) + e;
                sums[wr * 128 + j]  = sm[jt * 2 + e];
                accvs[wr * 128 + j] = av[jt * 2 + e];
            }
    }
    __syncthreads();

    // ---- final combine + output ----
    if (tid < 128) {
        int r = r0 + tid;
        if (r < RCNT) {
            float s = sums[tid] + sums[128 + tid];
            float a = accvs[tid] + accvs[128 + tid];
            out[b * RCNT + r] = (s > 0.f) ? a / s : 0.f;
        }
    }
}

extern "C" void kernel_launch(void* const* d_in, const int* in_sizes, int n_in,
                              void* d_out, int out_size) {
    const int*   poi_idx  = (const int*)d_in[0];
    const int*   hour     = (const int*)d_in[1];
    const float* lat      = (const float*)d_in[2];
    const float* lon      = (const float*)d_in[3];
    const float* t_min    = (const float*)d_in[4];
    const float* cent     = (const float*)d_in[5];
    const float* poi_emb  = (const float*)d_in[6];
    const float* time_emb = (const float*)d_in[7];
    const float* E_t      = (const float*)d_in[8];
    const float* E_d      = (const float*)d_in[9];
    const float* E_dm     = (const float*)d_in[10];
    const float* remb     = (const float*)d_in[11];
    const float* Wq       = (const float*)d_in[12];
    const float* Wk       = (const float*)d_in[13];
    const float* Wv       = (const float*)d_in[14];
    float* out = (float*)d_out;

    const int SMEM_A = 107776;
    const int SMEM_B = 55296;
    cudaFuncSetAttribute(attn_kernel,  cudaFuncAttributeMaxDynamicSharedMemorySize, SMEM_A);
    cudaFuncSetAttribute(match_kernel, cudaFuncAttributeMaxDynamicSharedMemorySize, SMEM_B);

    conv_E_kernel<<<256, 256>>>(remb);
    attn_kernel<<<BATCH, 256, SMEM_A>>>(poi_idx, hour, lat, lon, t_min,
                                        poi_emb, time_emb, E_t, E_d, Wq, Wk, Wv);
    match_kernel<<<dim3(8, BATCH), 256, SMEM_B>>>(poi_idx, lat, lon, cent,
                                                  E_dm, out);
}

// round 14
// speedup vs baseline: 5.7936x; 1.0163x over previous
#include <cuda_runtime.h>
#include <cuda_bf16.h>
#include <cstdint>
#include <math.h>

#define BATCH   1024
#define NSEQ    50
#define RCNT    1000
#define NPOIS   50000
#define DD      128
#define BST     136   // bf16 MMA tile row stride (elements)
#define VST     72    // V_T / attn bf16 row stride (elements)
#define DEG2RAD 0.017453292519943295f
#define KHALF   0.008726646259971648f   // 0.5 * DEG2RAD
#define BINFOLD 4013.7299f              // 12742 * 63 / 200
#define SCALE   0.08838834764831845f    // 1/sqrt(128)

// scratch: S = attn @ V (pre-scaled by 1/sqrt(D)), (B, N, D) bf16
__device__ __align__(16) __nv_bfloat16 g_S_bf[BATCH * NSEQ * DD];
// region_emb pre-converted to bf16, zero-padded to 1024 rows
__device__ __align__(16) __nv_bfloat16 g_E_bf[1024 * DD];
// Wq|Wk|Wv pre-converted to bf16
__device__ __align__(16) __nv_bfloat16 g_W_bf[3 * DD * DD];

__device__ __forceinline__ float interp2(const float2* t, float x) {
    int k = (int)x;
    float f = x - (float)k;
    float2 v = t[k];
    return fmaf(f, v.y, v.x);
}

__device__ __forceinline__ float coslat(float latdeg) {
    float r = latdeg * DEG2RAD;
    float r2 = r * r;
    return 1.f - 0.5f * r2 + r2 * r2 * (1.f / 24.f);
}

__device__ __forceinline__ uint32_t smem_u32(const void* p) {
    return (uint32_t)__cvta_generic_to_shared(p);
}

#define LDMX4(R, addr)                                                        \
    asm volatile("ldmatrix.sync.aligned.m8n8.x4.shared.b16 {%0,%1,%2,%3}, [%4];" \
                 : "=r"((R)[0]), "=r"((R)[1]), "=r"((R)[2]), "=r"((R)[3])      \
                 : "r"(addr))

#define MMA16816(C, A, B0, B1)                                                \
    asm volatile("mma.sync.aligned.m16n8k16.row.col.f32.bf16.bf16.f32 "       \
                 "{%0,%1,%2,%3},{%4,%5,%6,%7},{%8,%9},{%0,%1,%2,%3};"         \
                 : "+f"((C)[0]), "+f"((C)[1]), "+f"((C)[2]), "+f"((C)[3])      \
                 : "r"((A)[0]), "r"((A)[1]), "r"((A)[2]), "r"((A)[3]),         \
                   "r"(B0), "r"(B1))

// ------- Kernel 0: convert region_emb + Wq/Wk/Wv -> bf16 (E zero-padded) -------
// grid = 352, block = 256; idx in float2 units: [0,65536) E, [65536,90112) W
__global__ void conv_kernel(const float* __restrict__ remb,
                            const float* __restrict__ Wq,
                            const float* __restrict__ Wk,
                            const float* __restrict__ Wv) {
    int idx = blockIdx.x * 256 + threadIdx.x;
    if (idx < 65536) {
        int r = idx >> 6;
        float2 v = make_float2(0.f, 0.f);
        if (r < RCNT) v = ((const float2*)remb)[idx];
        *(__nv_bfloat162*)&g_E_bf[idx * 2] = __floats2bfloat162_rn(v.x, v.y);
    } else {
        int k = idx - 65536;            // 0..24575
        int p = k >> 13;                // 8192 float2 per W
        int off = k & 8191;
        const float* W = (p == 0) ? Wq : (p == 1) ? Wk : Wv;
        float2 v = ((const float2*)W)[off];
        *(__nv_bfloat162*)&g_W_bf[k * 2] = __floats2bfloat162_rn(v.x, v.y);
    }
}

// ---------------- Kernel 1: gather + bf16-MMA QKV + biased attention -> S(bf16) ----
// grid = B, block = 256 (8 warps), dyn smem = 107776 B
__global__ __launch_bounds__(256, 2)
void attn_kernel(const int* __restrict__ poi_idx, const int* __restrict__ hour,
                 const float* __restrict__ lat, const float* __restrict__ lon,
                 const float* __restrict__ t_min,
                 const float* __restrict__ poi_emb, const float* __restrict__ time_emb,
                 const float* __restrict__ E_t, const float* __restrict__ E_d) {
    extern __shared__ char smc[];
    __nv_bfloat16* x_bf  = (__nv_bfloat16*)(smc);            // 64 x 136 = 17408 B
    __nv_bfloat16* W_bf  = (__nv_bfloat16*)(smc + 17408);    // 128 x 136 = 34816 B
    __nv_bfloat16* Q_bf  = (__nv_bfloat16*)(smc + 52224);    // 64 x 136
    __nv_bfloat16* K_bf  = (__nv_bfloat16*)(smc + 69632);    // 64 x 136
    __nv_bfloat16* V_T   = (__nv_bfloat16*)(smc + 87040);    // 128 x 72 = 18432 B
    float* geo   = (float*)(smc + 105472);
    float* tv    = geo;            // 64
    float* yl    = geo + 64;
    float* xl    = geo + 128;
    float* cl    = geo + 192;
    float* padf  = geo + 256;
    float2* Et2  = (float2*)(geo + 320);   // 64 float2
    float2* Ed2  = (float2*)(geo + 448);   // 64 float2
    __nv_bfloat16* attn_bf = x_bf;          // alias, 64 x 72 (x dead by then)

    int b = blockIdx.x;
    int tid = threadIdx.x;
    int warp = tid >> 5, lane = tid & 31;

    if (tid < 64) {
        int t1 = (tid < 63) ? tid + 1 : 63;
        float e0 = E_t[tid];
        Et2[tid] = make_float2(e0, E_t[t1] - e0);
        float d0 = E_d[tid];
        Ed2[tid] = make_float2(d0, E_d[t1] - d0);
        if (tid < NSEQ) {
            int pi = poi_idx[b * NSEQ + tid];
            padf[tid] = (pi < 0) ? 1.f : 0.f;
            tv[tid] = t_min[b * NSEQ + tid];
            float lt = lat[b * NSEQ + tid];
            yl[tid] = lt * KHALF;
            xl[tid] = lon[b * NSEQ + tid] * KHALF;
            cl[tid] = coslat(lt);
        } else {
            padf[tid] = 1.f; tv[tid] = 0.f;
            yl[tid] = 0.f; xl[tid] = 0.f; cl[tid] = 1.f;
        }
    }
    // gather x = poi_emb + time_emb, bf16, rows >= 50 zero
    for (int idx = tid; idx < 64 * 64; idx += 256) {
        int row = idx >> 6, c2 = idx & 63;
        float2 v = make_float2(0.f, 0.f);
        if (row < NSEQ) {
            int pi = poi_idx[b * NSEQ + row];
            int ps, hs;
            if (pi < 0) { ps = NPOIS; hs = 0; }
            else        { ps = pi;    hs = hour[b * NSEQ + row]; }
            float2 p = *(const float2*)&poi_emb[ps * DD + c2 * 2];
            float2 t = *(const float2*)&time_emb[hs * DD + c2 * 2];
            v = make_float2(p.x + t.x, p.y + t.y);
        }
        *(__nv_bfloat162*)&x_bf[row * BST + c2 * 2] = __floats2bfloat162_rn(v.x, v.y);
    }

    // fragment geometry (shared by all MMA phases)
    int arow = lane & 15, acol = (lane >> 4) << 3;
    int bj   = (lane & 7) | ((lane >> 4) << 3);
    int bk   = ((lane >> 3) & 1) << 3;
    int trow = lane >> 2, tcol = (lane & 3) << 1;

    // ---- Phase B: QKV projections via MMA (loop over Wq, Wk, Wv) ----
    int nbase = (warp >> 2) * 32;
    int jbase = (warp & 3) * 32;
#pragma unroll 1
    for (int p = 0; p < 3; p++) {
        const __nv_bfloat16* Wg = g_W_bf + p * (DD * DD);
        for (int idx = tid; idx < 128 * 16; idx += 256) {
            int row = idx >> 4, c = idx & 15;
            uint4 v = *(const uint4*)&Wg[row * DD + c * 8];
            *(uint4*)&W_bf[row * BST + c * 8] = v;
        }
        __syncthreads();

        float acc[2][4][4];
#pragma unroll
        for (int a = 0; a < 2; a++)
#pragma unroll
            for (int c = 0; c < 4; c++)
#pragma unroll
                for (int e = 0; e < 4; e++) acc[a][c][e] = 0.f;

        uint32_t aA0 = smem_u32(&x_bf[(nbase + arow) * BST + acol]);
        uint32_t aA1 = smem_u32(&x_bf[(nbase + 16 + arow) * BST + acol]);
        uint32_t bA0 = smem_u32(&W_bf[(jbase + bj) * BST + bk]);
        uint32_t bA1 = smem_u32(&W_bf[(jbase + 16 + bj) * BST + bk]);
#pragma unroll
        for (int ks = 0; ks < 8; ks++) {
            uint32_t a0[4], a1[4], b0[4], b1[4];
            uint32_t koff = ks * 32;
            LDMX4(a0, aA0 + koff);
            LDMX4(a1, aA1 + koff);
            LDMX4(b0, bA0 + koff);
            LDMX4(b1, bA1 + koff);
            MMA16816(acc[0][0], a0, b0[0], b0[1]);
            MMA16816(acc[0][1], a0, b0[2], b0[3]);
            MMA16816(acc[0][2], a0, b1[0], b1[1]);
            MMA16816(acc[0][3], a0, b1[2], b1[3]);
            MMA16816(acc[1][0], a1, b0[0], b0[1]);
            MMA16816(acc[1][1], a1, b0[2], b0[3]);
            MMA16816(acc[1][2], a1, b1[0], b1[1]);
            MMA16816(acc[1][3], a1, b1[2], b1[3]);
        }

        if (p < 2) {
            __nv_bfloat16* dst = (p == 0) ? Q_bf : K_bf;
#pragma unroll
            for (int mi = 0; mi < 2; mi++)
#pragma unroll
                for (int rh = 0; rh < 2; rh++) {
                    int n = nbase + mi * 16 + trow + rh * 8;
#pragma unroll
                    for (int jt = 0; jt < 4; jt++) {
                        int d0 = jbase + jt * 8 + tcol;
                        *(__nv_bfloat162*)&dst[n * BST + d0] =
                            __floats2bfloat162_rn(acc[mi][jt][rh * 2], acc[mi][jt][rh * 2 + 1]);
                    }
                }
        } else {
#pragma unroll
            for (int mi = 0; mi < 2; mi++)
#pragma unroll
                for (int rh = 0; rh < 2; rh++) {
                    int n = nbase + mi * 16 + trow + rh * 8;
#pragma unroll
                    for (int jt = 0; jt < 4; jt++)
#pragma unroll
                        for (int e = 0; e < 2; e++) {
                            int d = jbase + jt * 8 + tcol + e;
                            V_T[d * VST + n] = __float2bfloat16(acc[mi][jt][rh * 2 + e]);
                        }
                }
        }
        __syncthreads();
    }

    // ---- Phase C: QK^T + bias + row softmax -> attn_bf (warps 0-3) ----
    if (warp < 4) {
        int nb = warp * 16;
        uint32_t aA = smem_u32(&Q_bf[(nb + arow) * BST + acol]);
        uint32_t bA[4];
#pragma unroll
        for (int t = 0; t < 4; t++)
            bA[t] = smem_u32(&K_bf[(t * 16 + bj) * BST + bk]);

        float acc[8][4];
#pragma unroll
        for (int t = 0; t < 8; t++)
#pragma unroll
            for (int e = 0; e < 4; e++) acc[t][e] = 0.f;

#pragma unroll
        for (int ks = 0; ks < 8; ks++) {
            uint32_t a[4];
            uint32_t koff = ks * 32;
            LDMX4(a, aA + koff);
#pragma unroll
            for (int t = 0; t < 4; t++) {
                uint32_t bb[4];
                LDMX4(bb, bA[t] + koff);
                MMA16816(acc[2 * t],     a, bb[0], bb[1]);
                MMA16816(acc[2 * t + 1], a, bb[2], bb[3]);
            }
        }

        // per-row bias + softmax (two rows per thread)
#pragma unroll
        for (int half = 0; half < 2; half++) {
            int n = nb + trow + half * 8;
            float tv_n = tv[n], y_n = yl[n], x_n = xl[n], c_n = cl[n];
            float vpn = 1.f - padf[n];
            float s[16];
#pragma unroll
            for (int t = 0; t < 8; t++)
#pragma unroll
                for (int e = 0; e < 2; e++) {
                    int m = t * 8 + tcol + e;
                    float vp = vpn * (1.f - padf[m]);
                    float dt = fabsf(tv_n - tv[m]) * vp;
                    float xt = fminf(dt * (63.f / 10080.f), 62.999996f);
                    float hl = yl[m] - y_n, ho = xl[m] - x_n;
                    float a2 = fmaf(hl, hl, c_n * cl[m] * ho * ho);
                    float sq = sqrtf(a2);
                    float bb = BINFOLD * sq;
                    float bin = fmaf(bb, a2 * (1.f / 6.f), bb) * vp;
                    float bias = interp2(Et2, xt) + interp2(Ed2, bin);
                    float v = acc[t][half * 2 + e] * SCALE + bias;
                    if (padf[m] > 0.5f) v = -1e30f;
                    s[t * 2 + e] = v;
                }
            float mx = -1e30f;
#pragma unroll
            for (int i = 0; i < 16; i++) mx = fmaxf(mx, s[i]);
            mx = fmaxf(mx, __shfl_xor_sync(0xffffffff, mx, 1));
            mx = fmaxf(mx, __shfl_xor_sync(0xffffffff, mx, 2));
            float sum = 0.f;
            float ex[16];
#pragma unroll
            for (int i = 0; i < 16; i++) {
                ex[i] = (s[i] > -1e29f) ? __expf(s[i] - mx) : 0.f;
                sum += ex[i];
            }
            sum += __shfl_xor_sync(0xffffffff, sum, 1);
            sum += __shfl_xor_sync(0xffffffff, sum, 2);
            float inv = (sum > 0.f) ? 1.f / sum : 0.f;
#pragma unroll
            for (int t = 0; t < 8; t++)
#pragma unroll
                for (int e = 0; e < 2; e++) {
                    int m = t * 8 + tcol + e;
                    attn_bf[n * VST + m] = __float2bfloat16(ex[t * 2 + e] * inv);
                }
        }
    }
    __syncthreads();

    // ---- Phase D: S = (attn @ V) * SCALE via MMA, store bf16 to gmem ----
    {
        int dbase = jbase;
        float acc[2][4][4];
#pragma unroll
        for (int a = 0; a < 2; a++)
#pragma unroll
            for (int c = 0; c < 4; c++)
#pragma unroll
                for (int e = 0; e < 4; e++) acc[a][c][e] = 0.f;

        uint32_t aA0 = smem_u32(&attn_bf[(nbase + arow) * VST + acol]);
        uint32_t aA1 = smem_u32(&attn_bf[(nbase + 16 + arow) * VST + acol]);
        uint32_t bA0 = smem_u32(&V_T[(dbase + bj) * VST + bk]);
        uint32_t bA1 = smem_u32(&V_T[(dbase + 16 + bj) * VST + bk]);
#pragma unroll
        for (int ks = 0; ks < 4; ks++) {
            uint32_t a0[4], a1[4], b0[4], b1[4];
            uint32_t koff = ks * 32;
            LDMX4(a0, aA0 + koff);
            LDMX4(a1, aA1 + koff);
            LDMX4(b0, bA0 + koff);
            LDMX4(b1, bA1 + koff);
            MMA16816(acc[0][0], a0, b0[0], b0[1]);
            MMA16816(acc[0][1], a0, b0[2], b0[3]);
            MMA16816(acc[0][2], a0, b1[0], b1[1]);
            MMA16816(acc[0][3], a0, b1[2], b1[3]);
            MMA16816(acc[1][0], a1, b0[0], b0[1]);
            MMA16816(acc[1][1], a1, b0[2], b0[3]);
            MMA16816(acc[1][2], a1, b1[0], b1[1]);
            MMA16816(acc[1][3], a1, b1[2], b1[3]);
        }
#pragma unroll
        for (int mi = 0; mi < 2; mi++)
#pragma unroll
            for (int rh = 0; rh < 2; rh++) {
                int n = nbase + mi * 16 + trow + rh * 8;
                if (n < NSEQ) {
#pragma unroll
                    for (int jt = 0; jt < 4; jt++) {
                        int d0 = dbase + jt * 8 + tcol;
                        *(__nv_bfloat162*)&g_S_bf[b * (NSEQ * DD) + n * DD + d0] =
                            __floats2bfloat162_rn(acc[mi][jt][rh * 2] * SCALE,
                                                  acc[mi][jt][rh * 2 + 1] * SCALE);
                    }
                }
            }
    }
}

// ------- Kernel 2: bf16 MMA match GEMM + bias + merge-scale softmax, 2 r-tiles ----
// grid = (4, B), block = 256 (8 warps), dyn smem = 56832 B
__global__ __launch_bounds__(256, 4)
void match_kernel(const int* __restrict__ poi_idx,
                  const float* __restrict__ lat, const float* __restrict__ lon,
                  const float* __restrict__ centroids,
                  const float* __restrict__ E_dm,
                  float* __restrict__ out) {
    extern __shared__ char smc[];
    __nv_bfloat16* S_bf = (__nv_bfloat16*)(smc);           // 64 x 136 = 17408 B
    __nv_bfloat16* E_bf = (__nv_bfloat16*)(smc + 17408);   // 128 x 136 = 34816 B
    // reduction triples alias E_bf (dead between MMA and next fill)
    float* mxA = (float*)(smc + 17408);            // [2][128]
    float* smA = (float*)(smc + 17408 + 1024);     // [2][128]
    float* avA = (float*)(smc + 17408 + 2048);     // [2][128]
    float* geo  = (float*)(smc + 52224);                   // 1152 floats = 4608 B
    float* yn   = geo;          // 64
    float* xn   = geo + 64;
    float* cn   = geo + 128;
    float* pn   = geo + 192;
    float* yr   = geo + 256;    // 256
    float* xr   = geo + 512;
    float* cr   = geo + 768;
    float2* Edm2 = (float2*)(geo + 1024);  // 64 float2

    int b = blockIdx.y;
    int r0 = blockIdx.x * 256;
    int tid = threadIdx.x;

    if (tid < 64) {
        int t1 = (tid < 63) ? tid + 1 : 63;
        float e0 = E_dm[tid];
        Edm2[tid] = make_float2(e0, E_dm[t1] - e0);
        if (tid < NSEQ) {
            pn[tid] = (poi_idx[b * NSEQ + tid] < 0) ? 1.f : 0.f;
            float lt = lat[b * NSEQ + tid];
            yn[tid] = lt * KHALF;
            xn[tid] = lon[b * NSEQ + tid] * KHALF;
            cn[tid] = coslat(lt);
        } else {
            pn[tid] = 1.f; yn[tid] = 0.f; xn[tid] = 0.f; cn[tid] = 1.f;
        }
    }
    // region geo for both 128-tiles (256 regions)
    if (tid < 256) {
        int r = r0 + tid;
        float lt = 0.f, ln = 0.f;
        if (r < RCNT) { lt = centroids[2 * r]; ln = centroids[2 * r + 1]; }
        yr[tid] = lt * KHALF; xr[tid] = ln * KHALF; cr[tid] = coslat(lt);
    }
    // S tile: raw bf16 copy (rows >= 50 zero)
    for (int idx = tid; idx < 64 * 16; idx += 256) {
        int row = idx >> 4, c = idx & 15;
        uint4 v = make_uint4(0u, 0u, 0u, 0u);
        if (row < NSEQ)
            v = *(const uint4*)&g_S_bf[b * (NSEQ * DD) + row * DD + c * 8];
        *(uint4*)&S_bf[row * BST + c * 8] = v;
    }
    // E tile for rt=0
    for (int idx = tid; idx < 128 * 16; idx += 256) {
        int row = idx >> 4, c = idx & 15;
        uint4 v = *(const uint4*)&g_E_bf[(r0 + row) * DD + c * 8];
        *(uint4*)&E_bf[row * BST + c * 8] = v;
    }
    __syncthreads();

    int warp = tid >> 5, lane = tid & 31;
    int wr = warp >> 2;            // warp row (n-half)
    int nbase = wr * 32;
    int jbase = (warp & 3) * 32;

    int arow = lane & 15, acol = (lane >> 4) << 3;
    int bj   = (lane & 7) | ((lane >> 4) << 3);
    int bk   = ((lane >> 3) & 1) << 3;
    int trow = lane >> 2, tcol = (lane & 3) << 1;

    uint32_t aAddr0 = smem_u32(&S_bf[(nbase + arow) * BST + acol]);
    uint32_t aAddr1 = smem_u32(&S_bf[(nbase + 16 + arow) * BST + acol]);
    uint32_t bAddr0 = smem_u32(&E_bf[(jbase + bj) * BST + bk]);
    uint32_t bAddr1 = smem_u32(&E_bf[(jbase + 16 + bj) * BST + bk]);

#pragma unroll 1
    for (int rt = 0; rt < 2; rt++) {
        int jt0 = rt * 128;   // offset into yr/xr/cr

        float acc[2][4][4];
#pragma unroll
        for (int a = 0; a < 2; a++)
#pragma unroll
            for (int c = 0; c < 4; c++)
#pragma unroll
                for (int e = 0; e < 4; e++) acc[a][c][e] = 0.f;

#pragma unroll
        for (int ks = 0; ks < 8; ks++) {
            uint32_t a0[4], a1[4], b0[4], b1[4];
            uint32_t koff = ks * 32;
            LDMX4(a0, aAddr0 + koff);
            LDMX4(a1, aAddr1 + koff);
            LDMX4(b0, bAddr0 + koff);
            LDMX4(b1, bAddr1 + koff);
            MMA16816(acc[0][0], a0, b0[0], b0[1]);
            MMA16816(acc[0][1], a0, b0[2], b0[3]);
            MMA16816(acc[0][2], a0, b1[0], b1[1]);
            MMA16816(acc[0][3], a0, b1[2], b1[3]);
            MMA16816(acc[1][0], a1, b0[0], b0[1]);
            MMA16816(acc[1][1], a1, b0[2], b0[3]);
            MMA16816(acc[1][2], a1, b1[0], b1[1]);
            MMA16816(acc[1][3], a1, b1[2], b1[3]);
        }
        __syncthreads();   // E_bf dead -> triples writable

        // ---- scores: acc += bias (pad rows -> -1e30) ----
#pragma unroll
        for (int mi = 0; mi < 2; mi++) {
#pragma unroll
            for (int rh = 0; rh < 2; rh++) {
                int n = nbase + mi * 16 + trow + rh * 8;
                float y_n = yn[n], x_n = xn[n], c_n = cn[n];
                bool pad = pn[n] > 0.5f;
#pragma unroll
                for (int jt = 0; jt < 4; jt++) {
#pragma unroll
                    for (int e = 0; e < 2; e++) {
                        int j = jt0 + jbase + jt * 8 + tcol + e;
                        float dy = y_n - yr[j], dx = x_n - xr[j];
                        float a2 = fmaf(dy, dy, c_n * cr[j] * dx * dx);
                        float sq = sqrtf(a2);
                        float bb = BINFOLD * sq;
                        float bin = fmaf(bb, a2 * (1.f / 6.f), bb);
                        float v = acc[mi][jt][rh * 2 + e] + interp2(Edm2, bin);
                        acc[mi][jt][rh * 2 + e] = pad ? -1e30f : v;
                    }
                }
            }
        }

        // ---- per-warp-row local max, exp, sum, accv; store (m,s,a) triple ----
        float mx[8], sm[8], av[8];
#pragma unroll
        for (int jt = 0; jt < 4; jt++)
#pragma unroll
            for (int e = 0; e < 2; e++) {
                float m = fmaxf(fmaxf(acc[0][jt][e], acc[0][jt][2 + e]),
                                fmaxf(acc[1][jt][e], acc[1][jt][2 + e]));
                m = fmaxf(m, __shfl_xor_sync(0xffffffff, m, 4));
                m = fmaxf(m, __shfl_xor_sync(0xffffffff, m, 8));
                m = fmaxf(m, __shfl_xor_sync(0xffffffff, m, 16));
                mx[jt * 2 + e] = m;
            }
#pragma unroll
        for (int i = 0; i < 8; i++) { sm[i] = 0.f; av[i] = 0.f; }
#pragma unroll
        for (int mi = 0; mi < 2; mi++)
#pragma unroll
            for (int jt = 0; jt < 4; jt++)
#pragma unroll
                for (int q = 0; q < 4; q++) {
                    int e = q & 1;
                    float v = acc[mi][jt][q];
                    float ex = (v > -1e29f) ? __expf(v - mx[jt * 2 + e]) : 0.f;
                    sm[jt * 2 + e] += ex;
                    av[jt * 2 + e] += ex * v;
                }
#pragma unroll
        for (int i = 0; i < 8; i++) {
            sm[i] += __shfl_xor_sync(0xffffffff, sm[i], 4);
            sm[i] += __shfl_xor_sync(0xffffffff, sm[i], 8);
            sm[i] += __shfl_xor_sync(0xffffffff, sm[i], 16);
            av[i] += __shfl_xor_sync(0xffffffff, av[i], 4);
            av[i] += __shfl_xor_sync(0xffffffff, av[i], 8);
            av[i] += __shfl_xor_sync(0xffffffff, av[i], 16);
        }
        if (lane < 4) {
#pragma unroll
            for (int jt = 0; jt < 4; jt++)
#pragma unroll
                for (int e = 0; e < 2; e++) {
                    int j = jbase + jt * 8 + (lane << 1) + e;
                    mxA[wr * 128 + j] = mx[jt * 2 + e];
                    smA[wr * 128 + j] = sm[jt * 2 + e];
                    avA[wr * 128 + j] = av[jt * 2 + e];
                }
        }
        __syncthreads();

        // ---- merge-scale combine + output ----
        if (tid < 128) {
            int r = r0 + jt0 + tid;
            if (r < RCNT) {
                float m1 = mxA[tid], m2 = mxA[128 + tid];
                float M = fmaxf(m1, m2);
                float w1 = (m1 > -1e29f) ? __expf(m1 - M) : 0.f;
                float w2 = (m2 > -1e29f) ? __expf(m2 - M) : 0.f;
                float s = smA[tid] * w1 + smA[128 + tid] * w2;
                float a = avA[tid] * w1 + avA[128 + tid] * w2;
                out[b * RCNT + r] = (s > 0.f) ? a / s : 0.f;
            }
        }
        __syncthreads();   // triples read; E_bf free for refill

        if (rt == 0) {
            // E tile for rt=1
            for (int idx = tid; idx < 128 * 16; idx += 256) {
                int row = idx >> 4, c = idx & 15;
                uint4 v = *(const uint4*)&g_E_bf[(r0 + 128 + row) * DD + c * 8];
                *(uint4*)&E_bf[row * BST + c * 8] = v;
            }
            __syncthreads();
        }
    }
}

extern "C" void kernel_launch(void* const* d_in, const int* in_sizes, int n_in,
                              void* d_out, int out_size) {
    const int*   poi_idx  = (const int*)d_in[0];
    const int*   hour     = (const int*)d_in[1];
    const float* lat      = (const float*)d_in[2];
    const float* lon      = (const float*)d_in[3];
    const float* t_min    = (const float*)d_in[4];
    const float* cent     = (const float*)d_in[5];
    const float* poi_emb  = (const float*)d_in[6];
    const float* time_emb = (const float*)d_in[7];
    const float* E_t      = (const float*)d_in[8];
    const float* E_d      = (const float*)d_in[9];
    const float* E_dm     = (const float*)d_in[10];
    const float* remb     = (const float*)d_in[11];
    const float* Wq       = (const float*)d_in[12];
    const float* Wk       = (const float*)d_in[13];
    const float* Wv       = (const float*)d_in[14];
    float* out = (float*)d_out;

    const int SMEM_A = 107776;
    const int SMEM_B = 56832;
    cudaFuncSetAttribute(attn_kernel,  cudaFuncAttributeMaxDynamicSharedMemorySize, SMEM_A);
    cudaFuncSetAttribute(match_kernel, cudaFuncAttributeMaxDynamicSharedMemorySize, SMEM_B);

    conv_kernel<<<352, 256>>>(remb, Wq, Wk, Wv);
    attn_kernel<<<BATCH, 256, SMEM_A>>>(poi_idx, hour, lat, lon, t_min,
                                        poi_emb, time_emb, E_t, E_d);
    match_kernel<<<dim3(4, BATCH), 256, SMEM_B>>>(poi_idx, lat, lon, cent,
                                                  E_dm, out);
}